// round 14
// baseline (speedup 1.0000x reference)
#include <cuda_runtime.h>
#include <cuda_fp16.h>
#include <cstdint>

#define L_INPUT 165142
#define KFILT   33
#define L0      (L_INPUT - KFILT + 1)   /* 165110 */
#define RDC     32
#define SDIM    512
#define QDIM    256
#define NL      45
#define FINAL   160000
#define KPAD    1472                    /* 45*32=1440 padded to 64-multiple */
#define WBLOB   29056                   /* per-layer packed weights bytes */

// ---------------- scratch (static device globals; no allocation allowed) ----
__device__ __half g_xah[(size_t)L0 * 32];
__device__ __half g_xal[(size_t)L0 * 32];
__device__ __half g_xbh[(size_t)L0 * 32];
__device__ __half g_xbl[(size_t)L0 * 32];
__device__ __half g_Ghi[(size_t)FINAL * KPAD];
__device__ __half g_Glo[(size_t)FINAL * KPAD];
__device__ __half g_Shi[(size_t)FINAL * SDIM];
__device__ __half g_Slo[(size_t)FINAL * SDIM];
__device__ __half g_Hhi[(size_t)FINAL * SDIM];
__device__ __half g_Hlo[(size_t)FINAL * SDIM];
__device__ __half g_WaH[SDIM * KPAD];
__device__ __half g_P1H[SDIM * SDIM];
__device__ __half g_P2H[QDIM * SDIM];
__device__ float g_bsum[SDIM];
__device__ __align__(16) char g_wblob[(size_t)NL * WBLOB];

// ---------------- helpers --------------------------------------------------
static __device__ __forceinline__ uint32_t smem_u32(const void* p) {
    uint32_t a;
    asm("{ .reg .u64 t; cvta.to.shared.u64 t, %1; cvt.u32.u64 %0, t; }"
        : "=r"(a) : "l"(p));
    return a;
}
static __device__ __forceinline__ void split_h(float v, __half& h, __half& l) {
    h = __float2half(v);
    l = __float2half(v - __half2float(h));
}
static __device__ __forceinline__ uint32_t sw(int t, int q) {
    return (uint32_t)((t << 6) + (((q ^ ((t >> 1) & 3))) << 4));
}

#define LDM4(R, a) \
    asm volatile("ldmatrix.sync.aligned.m8n8.x4.shared.b16 {%0,%1,%2,%3}, [%4];" \
        : "=r"((R)[0]), "=r"((R)[1]), "=r"((R)[2]), "=r"((R)[3]) : "r"(a))

#define MMA16816(C, A, B) \
    asm volatile("mma.sync.aligned.m16n8k16.row.col.f32.f16.f16.f32 " \
        "{%0,%1,%2,%3}, {%4,%5,%6,%7}, {%8,%9}, {%0,%1,%2,%3};" \
        : "+f"((C)[0]), "+f"((C)[1]), "+f"((C)[2]), "+f"((C)[3]) \
        : "r"((A)[0]), "r"((A)[1]), "r"((A)[2]), "r"((A)[3]), \
          "r"((B)[0]), "r"((B)[1]))

#define MMA16816H(C, A, B) \
    asm volatile("mma.sync.aligned.m16n8k16.row.col.f16.f16.f16.f16 " \
        "{%0,%1}, {%2,%3,%4,%5}, {%6,%7}, {%0,%1};" \
        : "+r"((C)[0]), "+r"((C)[1]) \
        : "r"((A)[0]), "r"((A)[1]), "r"((A)[2]), "r"((A)[3]), \
          "r"((B)[0]), "r"((B)[1]))

#define CPASYNC16(dst, src) \
    asm volatile("cp.async.cg.shared.global [%0], [%1], 16;" \
        :: "r"(dst), "l"(src) : "memory")

// ---------------- prep: weights (hi) for big GEMMs, sum skip bias ---------
__global__ __launch_bounds__(256) void prep_kernel(const float* __restrict__ wskip,
                                                   const float* __restrict__ bskip,
                                                   const float* __restrict__ wp1,
                                                   const float* __restrict__ wp2)
{
    int idx = blockIdx.x * 256 + threadIdx.x;
    if (idx < SDIM * KPAD) {
        int c = idx / KPAD, k = idx - c * KPAD;
        float v = 0.f;
        if (k < NL * RDC) {
            int i = k >> 5, r = k & 31;
            v = wskip[(size_t)i * SDIM * RDC + (size_t)c * RDC + r];
        }
        g_WaH[idx] = __float2half(v);
    }
    if (idx < SDIM * SDIM) g_P1H[idx] = __float2half(wp1[idx]);
    if (idx < QDIM * SDIM) g_P2H[idx] = __float2half(wp2[idx]);
    if (idx < SDIM) {
        float s = 0.f;
        #pragma unroll
        for (int i = 0; i < NL; i++) s += bskip[i * SDIM + idx];
        g_bsum[idx] = s;
    }
}

// ---------------- prep2: pack per-layer weights into swizzled blobs -------
__global__ __launch_bounds__(384) void prep2_kernel(const float* __restrict__ wt,
                                                    const float* __restrict__ bt,
                                                    const float* __restrict__ ws,
                                                    const float* __restrict__ bs,
                                                    const float* __restrict__ wd,
                                                    const float* __restrict__ bd)
{
    const int i = blockIdx.x;
    char* blob = g_wblob + (size_t)i * WBLOB;
    const float* wti = wt + (size_t)i * 3072;
    const float* wsi = ws + (size_t)i * 3072;
    const float* wdi = wd + (size_t)i * 1024;
    int tid = threadIdx.x;

    for (int idx = tid; idx < 6144; idx += 384) {
        int m = idx / 96, rem = idx - m * 96, r = rem / 3, j = rem - r * 3;
        float v = (m < 32) ? wti[m * 96 + r * 3 + j] : wsi[(m - 32) * 96 + r * 3 + j];
        __half h, l;
        split_h(v, h, l);
        uint32_t off = (uint32_t)(j * 4096) + sw(m, r >> 3) + (r & 7) * 2;
        *(__half*)(blob + off)         = h;
        *(__half*)(blob + 12288 + off) = l;
    }
    for (int idx = tid; idx < 1024; idx += 384) {
        int c = idx >> 5, r = idx & 31;
        __half h, l;
        split_h(wdi[idx], h, l);
        uint32_t off = sw(c, r >> 3) + (r & 7) * 2;
        *(__half*)(blob + 24576 + off) = h;
        *(__half*)(blob + 26624 + off) = l;
    }
    if (tid < 32) {
        float* bia = (float*)(blob + 28672);
        bia[tid]      = bt[i * 32 + tid];
        bia[32 + tid] = bs[i * 32 + tid];
        bia[64 + tid] = bd[i * 32 + tid];
    }
}

// ---------------- causal conv: 1 -> 32 ch, K=33; out time-major hi/lo ------
__global__ __launch_bounds__(256) void causal_kernel(const float* __restrict__ x,
                                                     const float* __restrict__ w,
                                                     const float* __restrict__ b,
                                                     __half* __restrict__ oh,
                                                     __half* __restrict__ ol)
{
    __shared__ float xsh[256 + KFILT - 1];
    __shared__ float wsh[KFILT * 32];
    __shared__ float bsh[32];
    int tid = threadIdx.x;
    int t0  = blockIdx.x * 256;

    for (int i = tid; i < 256 + KFILT - 1; i += 256) {
        int g = t0 + i;
        xsh[i] = (g < L_INPUT) ? x[g] : 0.f;
    }
    for (int i = tid; i < 32 * KFILT; i += 256) {
        int c = i / KFILT, k = i - c * KFILT;
        wsh[k * 32 + c] = w[i];
    }
    if (tid < 32) bsh[tid] = b[tid];
    __syncthreads();

    int c = tid & 31, lane = tid >> 5;
    for (int grp = 0; grp < 4; grp++) {
        int tl = lane * 32 + grp * 8;
        float acc[8];
        #pragma unroll
        for (int u = 0; u < 8; u++) acc[u] = bsh[c];
        #pragma unroll
        for (int k = 0; k < KFILT; k++) {
            float wv = wsh[k * 32 + c];
            #pragma unroll
            for (int u = 0; u < 8; u++) acc[u] += wv * xsh[tl + u + k];
        }
        #pragma unroll
        for (int u = 0; u < 8; u++) {
            int t = t0 + tl + u;
            if (t < L0) {
                __half h, l;
                split_h(acc[u], h, l);
                oh[(size_t)t * 32 + c] = h;
                ol[(size_t)t * 32 + c] = l;
            }
        }
    }
}

// ---------------- one layer pass over a staged 384-row tile ----------------
template<int D>
static __device__ __forceinline__ void layer_pass(
    char* smem, uint32_t sb,
    uint32_t IXH, uint32_t IXL, uint32_t SGH, uint32_t SGL, uint32_t BLOB,
    __half* __restrict__ Gh, __half* __restrict__ Gl,
    int t0, int cut, int rowLim,
    __half* __restrict__ xouth, __half* __restrict__ xoutl, int L_out)
{
    const int tid = threadIdx.x;
    const int l    = tid & 31;
    const int w    = tid >> 5;
    const int grp  = l >> 3, mrow = l & 7;
    const int tw   = w * 32;
    const float* bia = (const float*)(smem + BLOB + 28672);

    float acc[4][4][4];
    #pragma unroll
    for (int mi = 0; mi < 4; mi++) {
        float b0 = bia[mi * 16 + (l >> 2)];
        float b8 = bia[mi * 16 + (l >> 2) + 8];
        #pragma unroll
        for (int ni = 0; ni < 4; ni++) {
            acc[mi][ni][0] = b0; acc[mi][ni][1] = b0;
            acc[mi][ni][2] = b8; acc[mi][ni][3] = b8;
        }
    }

    #pragma unroll
    for (int j = 0; j < 3; j++) {
        #pragma unroll
        for (int kc = 0; kc < 2; kc++) {
            uint32_t a4[4][4], b1[4][2];
            #pragma unroll
            for (int h2 = 0; h2 < 2; h2++) {
                int t = tw + j * D + h2 * 16 + ((grp >> 1) << 3) + mrow;
                int q = kc * 2 + (grp & 1);
                uint32_t R[4];
                LDM4(R, sb + IXH + sw(t, q));
                b1[h2 * 2][0] = R[0]; b1[h2 * 2][1] = R[1];
                b1[h2 * 2 + 1][0] = R[2]; b1[h2 * 2 + 1][1] = R[3];
            }
            int tm = ((grp & 1) << 3) + mrow;
            int qa = kc * 2 + (grp >> 1);
            #pragma unroll
            for (int mi = 0; mi < 4; mi++)
                LDM4(a4[mi], sb + BLOB + j * 4096 + sw(mi * 16 + tm, qa));
            #pragma unroll
            for (int mi = 0; mi < 4; mi++)
                #pragma unroll
                for (int ni = 0; ni < 4; ni++)
                    MMA16816(acc[mi][ni], a4[mi], b1[ni]);
            #pragma unroll
            for (int mi = 0; mi < 4; mi++)
                LDM4(a4[mi], sb + BLOB + 12288 + j * 4096 + sw(mi * 16 + tm, qa));
            #pragma unroll
            for (int mi = 0; mi < 4; mi++)
                #pragma unroll
                for (int ni = 0; ni < 4; ni++)
                    MMA16816(acc[mi][ni], a4[mi], b1[ni]);
        }
    }

    #pragma unroll
    for (int mi = 0; mi < 2; mi++)
        #pragma unroll
        for (int ni = 0; ni < 4; ni++)
            #pragma unroll
            for (int jj = 0; jj < 4; jj++) {
                float a1 = fminf(fmaxf(acc[mi][ni][jj], -30.f), 30.f);
                float a2 = fminf(fmaxf(acc[mi + 2][ni][jj], -30.f), 30.f);
                float u  = 1.f + __expf(-2.f * a1);
                float vv = 1.f + __expf(-a2);
                float gv = __fdividef(2.f - u, u * vv);
                int t_loc = tw + ni * 8 + 2 * (l & 3) + (jj & 1);
                int c     = mi * 16 + (l >> 2) + ((jj >= 2) ? 8 : 0);
                __half h, lo2;
                split_h(gv, h, lo2);
                uint32_t off = sw(t_loc, c >> 3) + (c & 7) * 2;
                *(__half*)(smem + SGH + off) = h;
                *(__half*)(smem + SGL + off) = lo2;
            }
    __syncwarp();

    {
        int row = tw + l;
        int uo  = t0 + row - cut;
        if (row < rowLim && uo >= 0 && uo < FINAL) {
            char* dh = (char*)(Gh + (size_t)uo * KPAD);
            char* dl = (char*)(Gl + (size_t)uo * KPAD);
            #pragma unroll
            for (int q = 0; q < 4; q++) {
                *(uint4*)(dh + q * 16) = *(uint4*)(smem + SGH + sw(row, q));
                *(uint4*)(dl + q * 16) = *(uint4*)(smem + SGL + sw(row, q));
            }
        }
    }

    float dacc[2][4][4];
    uint32_t hacc[2][4][2];
    #pragma unroll
    for (int mi = 0; mi < 2; mi++) {
        float b0 = bia[64 + mi * 16 + (l >> 2)];
        float b8 = bia[64 + mi * 16 + (l >> 2) + 8];
        #pragma unroll
        for (int ni = 0; ni < 4; ni++) {
            dacc[mi][ni][0] = b0; dacc[mi][ni][1] = b0;
            dacc[mi][ni][2] = b8; dacc[mi][ni][3] = b8;
            hacc[mi][ni][0] = 0u; hacc[mi][ni][1] = 0u;
        }
    }
    #pragma unroll
    for (int kc = 0; kc < 2; kc++) {
        uint32_t a4[2][4], b1[4][2], b2[4][2];
        #pragma unroll
        for (int h2 = 0; h2 < 2; h2++) {
            int t = tw + h2 * 16 + ((grp >> 1) << 3) + mrow;
            int q = kc * 2 + (grp & 1);
            uint32_t R[4];
            LDM4(R, sb + SGH + sw(t, q));
            b1[h2 * 2][0] = R[0]; b1[h2 * 2][1] = R[1];
            b1[h2 * 2 + 1][0] = R[2]; b1[h2 * 2 + 1][1] = R[3];
            LDM4(R, sb + SGL + sw(t, q));
            b2[h2 * 2][0] = R[0]; b2[h2 * 2][1] = R[1];
            b2[h2 * 2 + 1][0] = R[2]; b2[h2 * 2 + 1][1] = R[3];
        }
        int tm = ((grp & 1) << 3) + mrow;
        int qa = kc * 2 + (grp >> 1);
        #pragma unroll
        for (int mi = 0; mi < 2; mi++)
            LDM4(a4[mi], sb + BLOB + 24576 + sw(mi * 16 + tm, qa));
        #pragma unroll
        for (int mi = 0; mi < 2; mi++)
            #pragma unroll
            for (int ni = 0; ni < 4; ni++) {
                MMA16816(dacc[mi][ni], a4[mi], b1[ni]);
                MMA16816H(hacc[mi][ni], a4[mi], b2[ni]);
            }
        #pragma unroll
        for (int mi = 0; mi < 2; mi++)
            LDM4(a4[mi], sb + BLOB + 26624 + sw(mi * 16 + tm, qa));
        #pragma unroll
        for (int mi = 0; mi < 2; mi++)
            #pragma unroll
            for (int ni = 0; ni < 4; ni++)
                MMA16816H(hacc[mi][ni], a4[mi], b1[ni]);
    }
    __syncwarp();

    #pragma unroll
    for (int mi = 0; mi < 2; mi++)
        #pragma unroll
        for (int ni = 0; ni < 4; ni++) {
            __half2 h01 = *(__half2*)&hacc[mi][ni][0];
            __half2 h23 = *(__half2*)&hacc[mi][ni][1];
            float cr[4] = {__low2float(h01), __high2float(h01),
                           __low2float(h23), __high2float(h23)};
            #pragma unroll
            for (int jj = 0; jj < 4; jj++) {
                int t_loc = tw + ni * 8 + 2 * (l & 3) + (jj & 1);
                int c     = mi * 16 + (l >> 2) + ((jj >= 2) ? 8 : 0);
                uint32_t offx = sw(t_loc + D, c >> 3) + (c & 7) * 2;
                float xv = __half2float(*(__half*)(smem + IXH + offx))
                         + __half2float(*(__half*)(smem + IXL + offx));
                float ov = dacc[mi][ni][jj] + cr[jj] + xv;
                __half h, lo2;
                split_h(ov, h, lo2);
                uint32_t off = sw(t_loc, c >> 3) + (c & 7) * 2;
                *(__half*)(smem + SGH + off) = h;
                *(__half*)(smem + SGL + off) = lo2;
            }
        }
    __syncwarp();

    if (xouth) {
        int row = tw + l;
        int t   = t0 + row;
        if (row < rowLim && t < L_out) {
            char* dh = (char*)(xouth + (size_t)t * 32);
            char* dl = (char*)(xoutl + (size_t)t * 32);
            #pragma unroll
            for (int q = 0; q < 4; q++) {
                *(uint4*)(dh + q * 16) = *(uint4*)(smem + SGH + sw(row, q));
                *(uint4*)(dl + q * 16) = *(uint4*)(smem + SGL + sw(row, q));
            }
        }
    }
}

// ---------------- single-layer kernel --------------------------------------
template<int D>
__global__ __launch_bounds__(384, 1) void layer_mma(
    const __half* __restrict__ xinh, const __half* __restrict__ xinl,
    __half* __restrict__ xouth, __half* __restrict__ xoutl,
    const char* __restrict__ wblob,
    __half* __restrict__ Gh, __half* __restrict__ Gl,
    int L_in, int L_out, int cut)
{
    constexpr int RT = 384 + 2 * D;
    constexpr int XH  = 0;
    constexpr int XL  = RT * 64;
    constexpr int BL  = 2 * RT * 64;
    constexpr int STH = BL + WBLOB;
    constexpr int STL = STH + 24576;

    extern __shared__ char smem[];
    const uint32_t sb = smem_u32(smem);
    const int tid = threadIdx.x;
    const int t0  = blockIdx.x * 384;

    for (int idx = tid; idx < WBLOB / 16; idx += 384)
        CPASYNC16(sb + BL + idx * 16, wblob + idx * 16);

    for (int idx = tid; idx < RT * 4; idx += 384) {
        int t = idx >> 2, q = idx & 3;
        uint32_t so = sw(t, q);
        if (t0 + t < L_in) {
            CPASYNC16(sb + XH + so, xinh + (size_t)(t0 + t) * 32 + q * 8);
            CPASYNC16(sb + XL + so, xinl + (size_t)(t0 + t) * 32 + q * 8);
        } else {
            uint4 z = make_uint4(0, 0, 0, 0);
            *(uint4*)(smem + XH + so) = z;
            *(uint4*)(smem + XL + so) = z;
        }
    }
    asm volatile("cp.async.commit_group;" ::: "memory");
    asm volatile("cp.async.wait_group 0;" ::: "memory");
    __syncthreads();

    layer_pass<D>(smem, sb, XH, XL, STH, STL, BL, Gh, Gl,
                  t0, cut, 384, xouth, xoutl, L_out);
}

#define LAYER_SMEM_B(D_) (2 * (384 + 2 * (D_)) * 64 + WBLOB + 384 * 64 * 2)

// ---------------- fused two-layer kernel (dilations D1, D2=2*D1) -----------
template<int D1, int D2>
__global__ __launch_bounds__(384, 1) void layer2_mma(
    const __half* __restrict__ xinh, const __half* __restrict__ xinl,
    __half* __restrict__ xouth, __half* __restrict__ xoutl,
    const char* __restrict__ wblob,
    __half* __restrict__ Gh, __half* __restrict__ Gl,
    int L_in, int L_out2, int cut1, int cut2)
{
    constexpr int RT1  = 384 + 2 * D1;
    constexpr int SRT  = 384 + 2 * D2;
    constexpr int SOUT = 384 - 2 * D2;
    constexpr int XH  = 0;
    constexpr int XL  = RT1 * 64;
    constexpr int BL  = 2 * RT1 * 64;
    constexpr int STH = BL + 2 * WBLOB;
    constexpr int STL = STH + SRT * 64;

    extern __shared__ char smem[];
    const uint32_t sb = smem_u32(smem);
    const int tid = threadIdx.x;
    const int t0  = blockIdx.x * SOUT;

    for (int idx = tid; idx < 2 * WBLOB / 16; idx += 384)
        CPASYNC16(sb + BL + idx * 16, wblob + idx * 16);

    for (int idx = tid; idx < RT1 * 4; idx += 384) {
        int t = idx >> 2, q = idx & 3;
        uint32_t so = sw(t, q);
        if (t0 + t < L_in) {
            CPASYNC16(sb + XH + so, xinh + (size_t)(t0 + t) * 32 + q * 8);
            CPASYNC16(sb + XL + so, xinl + (size_t)(t0 + t) * 32 + q * 8);
        } else {
            uint4 z = make_uint4(0, 0, 0, 0);
            *(uint4*)(smem + XH + so) = z;
            *(uint4*)(smem + XL + so) = z;
        }
    }
    asm volatile("cp.async.commit_group;" ::: "memory");
    asm volatile("cp.async.wait_group 0;" ::: "memory");
    __syncthreads();

    layer_pass<D1>(smem, sb, XH, XL, STH, STL, BL, Gh, Gl,
                   t0, cut1, 384, (__half*)nullptr, (__half*)nullptr, 0);
    __syncthreads();
    layer_pass<D2>(smem, sb, STH, STL, XH, XL, BL + WBLOB, Gh + 32, Gl + 32,
                   t0, cut2, SOUT, xouth, xoutl, L_out2);
}

#define LAYER2_SMEM_B(D1_, D2_) (2 * (384 + 2 * (D1_)) * 64 + 2 * WBLOB \
                                 + 2 * (384 + 2 * (D2_)) * 64)

// ---------------- GEMM: Ah*(Bh+Bl), 2-stage ring, 2 CTAs/SM ---------------
#define GSTG  49152
#define GSMEM (2 * GSTG)
__global__ __launch_bounds__(512, 2) void gemm_mma(
    const __half* __restrict__ Ah,
    const __half* __restrict__ Bh, const __half* __restrict__ Bl,
    const float* __restrict__ bias, int Kstr, int NC, int mode,
    __half* __restrict__ Ch, __half* __restrict__ Cl, int Cstr,
    float* __restrict__ Cf)
{
    extern __shared__ char smem[];
    const uint32_t sb = smem_u32(smem);
    const int tid = threadIdx.x;
    const int m0 = blockIdx.x << 7, n0 = blockIdx.y << 7;
    const int lane = tid & 31;
    const int wm = (tid >> 5) & 3, wn = tid >> 7;

    float acc[8][4];
    uint32_t hacc[8][2];
    #pragma unroll
    for (int i = 0; i < 8; i++) {
        #pragma unroll
        for (int j = 0; j < 4; j++) acc[i][j] = 0.f;
        hacc[i][0] = 0u; hacc[i][1] = 0u;
    }

    auto issue = [&](int c) {
        uint32_t buf = (uint32_t)(c & 1) * GSTG;
        int kc0 = c << 6;
        int rloc = tid >> 3, q = tid & 7;
        #pragma unroll
        for (int it = 0; it < 6; it++) {
            const int region = it >> 1;
            int rr = ((it & 1) << 6) + rloc;
            const __half* src;
            if      (region == 0) src = Ah + (size_t)(m0 + rr) * Kstr + kc0 + q * 8;
            else if (region == 1) src = Bh + (size_t)(n0 + rr) * Kstr + kc0 + q * 8;
            else                  src = Bl + (size_t)(n0 + rr) * Kstr + kc0 + q * 8;
            uint32_t off = (uint32_t)(rr * 128 + q * 16);
            off ^= (off >> 3) & 0x70;
            CPASYNC16(sb + buf + region * 16384u + off, src);
        }
        asm volatile("cp.async.commit_group;" ::: "memory");
    };

    issue(0);
    for (int c = 0; c < NC; c++) {
        if (c + 1 < NC) {
            issue(c + 1);
            asm volatile("cp.async.wait_group 1;" ::: "memory");
        } else {
            asm volatile("cp.async.wait_group 0;" ::: "memory");
        }
        __syncthreads();
        const uint32_t buf = sb + (uint32_t)(c & 1) * GSTG;

        #pragma unroll
        for (int ks = 0; ks < 4; ks++) {
            uint32_t ah[2][4], bh[4][2], bl2[4][2];
            #pragma unroll
            for (int mi = 0; mi < 2; mi++) {
                uint32_t row = wm * 32 + mi * 16 + (lane & 15);
                uint32_t ch  = ks * 2 + (lane >> 4);
                uint32_t off = row * 128 + ch * 16;
                off ^= (off >> 3) & 0x70;
                LDM4(ah[mi], buf + off);
            }
            #pragma unroll
            for (int nj = 0; nj < 2; nj++) {
                uint32_t row = wn * 32 + nj * 16 + (lane & 7) + ((lane >> 4) << 3);
                uint32_t ch  = ks * 2 + ((lane >> 3) & 1);
                uint32_t off = row * 128 + ch * 16;
                off ^= (off >> 3) & 0x70;
                uint32_t r4[4];
                LDM4(r4, buf + 16384u + off);
                bh[nj * 2][0] = r4[0]; bh[nj * 2][1] = r4[1];
                bh[nj * 2 + 1][0] = r4[2]; bh[nj * 2 + 1][1] = r4[3];
                LDM4(r4, buf + 32768u + off);
                bl2[nj * 2][0] = r4[0]; bl2[nj * 2][1] = r4[1];
                bl2[nj * 2 + 1][0] = r4[2]; bl2[nj * 2 + 1][1] = r4[3];
            }
            #pragma unroll
            for (int mi = 0; mi < 2; mi++)
                #pragma unroll
                for (int nt = 0; nt < 4; nt++) {
                    float*    C = acc[mi * 4 + nt];
                    uint32_t* H = hacc[mi * 4 + nt];
                    MMA16816(C, ah[mi], bh[nt]);
                    MMA16816H(H, ah[mi], bl2[nt]);
                }
        }
        __syncthreads();
    }

    float* cs = (float*)smem;
    #pragma unroll
    for (int mi = 0; mi < 2; mi++)
        #pragma unroll
        for (int nt = 0; nt < 4; nt++) {
            float*    C = acc[mi * 4 + nt];
            uint32_t* H = hacc[mi * 4 + nt];
            __half2 h01 = *(__half2*)&H[0];
            __half2 h23 = *(__half2*)&H[1];
            int mrow = wm * 32 + mi * 16 + (lane >> 2);
            int ncol = wn * 32 + nt * 8 + 2 * (lane & 3);
            cs[ncol * 132 + mrow]           = C[0] + __low2float(h01);
            cs[(ncol + 1) * 132 + mrow]     = C[1] + __high2float(h01);
            cs[ncol * 132 + mrow + 8]       = C[2] + __low2float(h23);
            cs[(ncol + 1) * 132 + mrow + 8] = C[3] + __high2float(h23);
        }
    __syncthreads();

    if (mode) {
        #pragma unroll
        for (int it = 0; it < 16; it++) {
            int idx = it * 512 + tid;
            int n = idx >> 6, mp = idx & 63;
            float2 v2 = *(float2*)&cs[n * 132 + 2 * mp];
            float b0 = __ldg(bias + m0 + 2 * mp);
            float b1 = __ldg(bias + m0 + 2 * mp + 1);
            float v0 = fmaxf(v2.x + b0, 0.f);
            float v1 = fmaxf(v2.y + b1, 0.f);
            __half h0, l0, h1, l1;
            split_h(v0, h0, l0);
            split_h(v1, h1, l1);
            uint32_t ph = (uint32_t)__half_as_ushort(h0) |
                          ((uint32_t)__half_as_ushort(h1) << 16);
            uint32_t pl = (uint32_t)__half_as_ushort(l0) |
                          ((uint32_t)__half_as_ushort(l1) << 16);
            size_t o = (size_t)(n0 + n) * Cstr + m0 + 2 * mp;
            *(uint32_t*)(Ch + o) = ph;
            *(uint32_t*)(Cl + o) = pl;
        }
    } else {
        #pragma unroll
        for (int it = 0; it < 32; it++) {
            int idx = it * 512 + tid;
            int n = idx & 127, m = idx >> 7;
            float v = cs[n * 132 + m] + __ldg(bias + m0 + m);
            Cf[(size_t)(m0 + m) * FINAL + n0 + n] = v;
        }
    }
}

// ---------------- launch --------------------------------------------------
extern "C" void kernel_launch(void* const* d_in, const int* in_sizes, int n_in,
                              void* d_out, int out_size)
{
    const float* x        = (const float*)d_in[0];
    const float* w_causal = (const float*)d_in[1];
    const float* b_causal = (const float*)d_in[2];
    const float* w_tanh   = (const float*)d_in[3];
    const float* b_tanh   = (const float*)d_in[4];
    const float* w_sig    = (const float*)d_in[5];
    const float* b_sig    = (const float*)d_in[6];
    const float* w_skip   = (const float*)d_in[7];
    const float* b_skip   = (const float*)d_in[8];
    const float* w_dense  = (const float*)d_in[9];
    const float* b_dense  = (const float*)d_in[10];
    const float* w_post1  = (const float*)d_in[11];
    const float* b_post1  = (const float*)d_in[12];
    const float* w_post2  = (const float*)d_in[13];
    const float* b_post2  = (const float*)d_in[14];

    float *bsum;
    __half *xah, *xal, *xbh, *xbl;
    __half *Ghi, *Glo, *Shi, *Slo, *Hhi, *Hlo;
    __half *WaH, *P1H, *P2H;
    char* wblob;
    cudaGetSymbolAddress((void**)&xah, g_xah);
    cudaGetSymbolAddress((void**)&xal, g_xal);
    cudaGetSymbolAddress((void**)&xbh, g_xbh);
    cudaGetSymbolAddress((void**)&xbl, g_xbl);
    cudaGetSymbolAddress((void**)&Ghi, g_Ghi);
    cudaGetSymbolAddress((void**)&Glo, g_Glo);
    cudaGetSymbolAddress((void**)&Shi, g_Shi);
    cudaGetSymbolAddress((void**)&Slo, g_Slo);
    cudaGetSymbolAddress((void**)&Hhi, g_Hhi);
    cudaGetSymbolAddress((void**)&Hlo, g_Hlo);
    cudaGetSymbolAddress((void**)&WaH, g_WaH);
    cudaGetSymbolAddress((void**)&P1H, g_P1H);
    cudaGetSymbolAddress((void**)&P2H, g_P2H);
    cudaGetSymbolAddress((void**)&bsum, g_bsum);
    cudaGetSymbolAddress((void**)&wblob, g_wblob);

    cudaFuncSetAttribute(gemm_mma,
                         cudaFuncAttributeMaxDynamicSharedMemorySize, GSMEM);

    prep_kernel<<<(SDIM * KPAD + 255) / 256, 256>>>(w_skip, b_skip, w_post1, w_post2);
    prep2_kernel<<<NL, 384>>>(w_tanh, b_tanh, w_sig, b_sig, w_dense, b_dense);
    causal_kernel<<<(L0 + 255) / 256, 256>>>(x, w_causal, b_causal, xah, xal);

    __half *curh = xah, *curl = xal, *nxth = xbh, *nxtl = xbl;
    int L = L0;
    int i = 0;
    while (i < NL) {
        int k = i % 9;
        int d = 1 << k;
        bool fuse = (i + 1 < NL) && (k == 0 || k == 2 || k == 4);
        if (fuse) {
            int d2   = d * 2;
            int Lmid = L - 2 * d;
            int Lout2 = Lmid - 2 * d2;
            int cut1 = (Lmid - FINAL) / 2;
            int cut2 = (Lout2 - FINAL) / 2;
            int SOUT = 384 - 2 * d2;

            void (*kfn)(const __half*, const __half*, __half*, __half*,
                        const char*, __half*, __half*, int, int, int, int) = nullptr;
            size_t smem = 0;
            switch (d) {
                case 1:  kfn = layer2_mma<1, 2>;   smem = LAYER2_SMEM_B(1, 2);   break;
                case 4:  kfn = layer2_mma<4, 8>;   smem = LAYER2_SMEM_B(4, 8);   break;
                case 16: kfn = layer2_mma<16, 32>; smem = LAYER2_SMEM_B(16, 32); break;
            }
            cudaFuncSetAttribute(kfn, cudaFuncAttributeMaxDynamicSharedMemorySize,
                                 (int)smem);
            kfn<<<(Lout2 + SOUT - 1) / SOUT, 384, smem>>>(
                curh, curl, nxth, nxtl,
                wblob + (size_t)i * WBLOB,
                Ghi + i * 32, Glo + i * 32,
                L, Lout2, cut1, cut2);
            L = Lout2;
            i += 2;
        } else {
            int Lout = L - 2 * d;
            int cut  = (Lout - FINAL) / 2;
            void (*kfn)(const __half*, const __half*, __half*, __half*,
                        const char*, __half*, __half*, int, int, int) = nullptr;
            size_t smem = 0;
            switch (d) {
                case 1:   kfn = layer_mma<1>;   smem = LAYER_SMEM_B(1);   break;
                case 2:   kfn = layer_mma<2>;   smem = LAYER_SMEM_B(2);   break;
                case 4:   kfn = layer_mma<4>;   smem = LAYER_SMEM_B(4);   break;
                case 8:   kfn = layer_mma<8>;   smem = LAYER_SMEM_B(8);   break;
                case 16:  kfn = layer_mma<16>;  smem = LAYER_SMEM_B(16);  break;
                case 32:  kfn = layer_mma<32>;  smem = LAYER_SMEM_B(32);  break;
                case 64:  kfn = layer_mma<64>;  smem = LAYER_SMEM_B(64);  break;
                case 128: kfn = layer_mma<128>; smem = LAYER_SMEM_B(128); break;
                case 256: kfn = layer_mma<256>; smem = LAYER_SMEM_B(256); break;
            }
            cudaFuncSetAttribute(kfn, cudaFuncAttributeMaxDynamicSharedMemorySize,
                                 (int)smem);
            kfn<<<(Lout + 383) / 384, 384, smem>>>(
                curh, curl, nxth, nxtl,
                wblob + (size_t)i * WBLOB,
                Ghi + i * 32, Glo + i * 32,
                L, Lout, cut);
            L = Lout;
            i += 1;
        }
        __half* t;
        t = curh; curh = nxth; nxth = t;
        t = curl; curl = nxtl; nxtl = t;
    }

    // skip GEMM: S = relu(Wa @ G + bsum)   M=512, K=1472, N=160000
    gemm_mma<<<dim3(SDIM / 128, FINAL / 128), 512, GSMEM>>>(
        WaH, Ghi, Glo, bsum, KPAD, KPAD / 64, 1, Shi, Slo, SDIM, nullptr);
    // post1: H = relu(W1 @ S + b1)         M=512, K=512
    gemm_mma<<<dim3(SDIM / 128, FINAL / 128), 512, GSMEM>>>(
        P1H, Shi, Slo, b_post1, SDIM, SDIM / 64, 1, Hhi, Hlo, SDIM, nullptr);
    // post2: out = W2 @ H + b2             M=256, K=512, fp32 channel-major
    gemm_mma<<<dim3(QDIM / 128, FINAL / 128), 512, GSMEM>>>(
        P2H, Hhi, Hlo, b_post2, SDIM, SDIM / 64, 0, nullptr, nullptr, 0,
        (float*)d_out);
}

// round 15
// speedup vs baseline: 1.2350x; 1.2350x over previous
#include <cuda_runtime.h>
#include <cuda_fp16.h>
#include <cstdint>

#define L_INPUT 165142
#define KFILT   33
#define L0      (L_INPUT - KFILT + 1)   /* 165110 */
#define RDC     32
#define SDIM    512
#define QDIM    256
#define NL      45
#define FINAL   160000
#define KPAD    1472                    /* 45*32=1440 padded to 64-multiple */
#define WBLOB   29056                   /* per-layer packed weights bytes */

// ---------------- scratch (static device globals; no allocation allowed) ----
__device__ __half g_xah[(size_t)L0 * 32];
__device__ __half g_xal[(size_t)L0 * 32];
__device__ __half g_xbh[(size_t)L0 * 32];
__device__ __half g_xbl[(size_t)L0 * 32];
__device__ __half g_Ghi[(size_t)FINAL * KPAD];
__device__ __half g_Glo[(size_t)FINAL * KPAD];
__device__ __half g_Shi[(size_t)FINAL * SDIM];
__device__ __half g_Slo[(size_t)FINAL * SDIM];
__device__ __half g_Hhi[(size_t)FINAL * SDIM];
__device__ __half g_Hlo[(size_t)FINAL * SDIM];
__device__ __half g_WaH[SDIM * KPAD];
__device__ __half g_P1H[SDIM * SDIM];
__device__ __half g_P2H[QDIM * SDIM];
__device__ float g_bsum[SDIM];
__device__ __align__(16) char g_wblob[(size_t)NL * WBLOB];

// ---------------- helpers --------------------------------------------------
static __device__ __forceinline__ uint32_t smem_u32(const void* p) {
    uint32_t a;
    asm("{ .reg .u64 t; cvta.to.shared.u64 t, %1; cvt.u32.u64 %0, t; }"
        : "=r"(a) : "l"(p));
    return a;
}
static __device__ __forceinline__ void split_h(float v, __half& h, __half& l) {
    h = __float2half(v);
    l = __float2half(v - __half2float(h));
}
static __device__ __forceinline__ uint32_t sw(int t, int q) {
    return (uint32_t)((t << 6) + (((q ^ ((t >> 1) & 3))) << 4));
}

#define LDM4(R, a) \
    asm volatile("ldmatrix.sync.aligned.m8n8.x4.shared.b16 {%0,%1,%2,%3}, [%4];" \
        : "=r"((R)[0]), "=r"((R)[1]), "=r"((R)[2]), "=r"((R)[3]) : "r"(a))

#define MMA16816(C, A, B) \
    asm volatile("mma.sync.aligned.m16n8k16.row.col.f32.f16.f16.f32 " \
        "{%0,%1,%2,%3}, {%4,%5,%6,%7}, {%8,%9}, {%0,%1,%2,%3};" \
        : "+f"((C)[0]), "+f"((C)[1]), "+f"((C)[2]), "+f"((C)[3]) \
        : "r"((A)[0]), "r"((A)[1]), "r"((A)[2]), "r"((A)[3]), \
          "r"((B)[0]), "r"((B)[1]))

#define MMA16816H(C, A, B) \
    asm volatile("mma.sync.aligned.m16n8k16.row.col.f16.f16.f16.f16 " \
        "{%0,%1}, {%2,%3,%4,%5}, {%6,%7}, {%0,%1};" \
        : "+r"((C)[0]), "+r"((C)[1]) \
        : "r"((A)[0]), "r"((A)[1]), "r"((A)[2]), "r"((A)[3]), \
          "r"((B)[0]), "r"((B)[1]))

#define CPASYNC16(dst, src) \
    asm volatile("cp.async.cg.shared.global [%0], [%1], 16;" \
        :: "r"(dst), "l"(src) : "memory")

// ---------------- prep: weights (hi) for big GEMMs, sum skip bias ---------
__global__ __launch_bounds__(256) void prep_kernel(const float* __restrict__ wskip,
                                                   const float* __restrict__ bskip,
                                                   const float* __restrict__ wp1,
                                                   const float* __restrict__ wp2)
{
    int idx = blockIdx.x * 256 + threadIdx.x;
    if (idx < SDIM * KPAD) {
        int c = idx / KPAD, k = idx - c * KPAD;
        float v = 0.f;
        if (k < NL * RDC) {
            int i = k >> 5, r = k & 31;
            v = wskip[(size_t)i * SDIM * RDC + (size_t)c * RDC + r];
        }
        g_WaH[idx] = __float2half(v);
    }
    if (idx < SDIM * SDIM) g_P1H[idx] = __float2half(wp1[idx]);
    if (idx < QDIM * SDIM) g_P2H[idx] = __float2half(wp2[idx]);
    if (idx < SDIM) {
        float s = 0.f;
        #pragma unroll
        for (int i = 0; i < NL; i++) s += bskip[i * SDIM + idx];
        g_bsum[idx] = s;
    }
}

// ---------------- prep2: pack per-layer weights into swizzled blobs -------
__global__ __launch_bounds__(384) void prep2_kernel(const float* __restrict__ wt,
                                                    const float* __restrict__ bt,
                                                    const float* __restrict__ ws,
                                                    const float* __restrict__ bs,
                                                    const float* __restrict__ wd,
                                                    const float* __restrict__ bd)
{
    const int i = blockIdx.x;
    char* blob = g_wblob + (size_t)i * WBLOB;
    const float* wti = wt + (size_t)i * 3072;
    const float* wsi = ws + (size_t)i * 3072;
    const float* wdi = wd + (size_t)i * 1024;
    int tid = threadIdx.x;

    for (int idx = tid; idx < 6144; idx += 384) {
        int m = idx / 96, rem = idx - m * 96, r = rem / 3, j = rem - r * 3;
        float v = (m < 32) ? wti[m * 96 + r * 3 + j] : wsi[(m - 32) * 96 + r * 3 + j];
        __half h, l;
        split_h(v, h, l);
        uint32_t off = (uint32_t)(j * 4096) + sw(m, r >> 3) + (r & 7) * 2;
        *(__half*)(blob + off)         = h;
        *(__half*)(blob + 12288 + off) = l;
    }
    for (int idx = tid; idx < 1024; idx += 384) {
        int c = idx >> 5, r = idx & 31;
        __half h, l;
        split_h(wdi[idx], h, l);
        uint32_t off = sw(c, r >> 3) + (r & 7) * 2;
        *(__half*)(blob + 24576 + off) = h;
        *(__half*)(blob + 26624 + off) = l;
    }
    if (tid < 32) {
        float* bia = (float*)(blob + 28672);
        bia[tid]      = bt[i * 32 + tid];
        bia[32 + tid] = bs[i * 32 + tid];
        bia[64 + tid] = bd[i * 32 + tid];
    }
}

// ---------------- causal conv: 1 -> 32 ch, K=33; out time-major hi/lo ------
__global__ __launch_bounds__(256) void causal_kernel(const float* __restrict__ x,
                                                     const float* __restrict__ w,
                                                     const float* __restrict__ b,
                                                     __half* __restrict__ oh,
                                                     __half* __restrict__ ol)
{
    __shared__ float xsh[256 + KFILT - 1];
    __shared__ float wsh[KFILT * 32];
    __shared__ float bsh[32];
    int tid = threadIdx.x;
    int t0  = blockIdx.x * 256;

    for (int i = tid; i < 256 + KFILT - 1; i += 256) {
        int g = t0 + i;
        xsh[i] = (g < L_INPUT) ? x[g] : 0.f;
    }
    for (int i = tid; i < 32 * KFILT; i += 256) {
        int c = i / KFILT, k = i - c * KFILT;
        wsh[k * 32 + c] = w[i];
    }
    if (tid < 32) bsh[tid] = b[tid];
    __syncthreads();

    int c = tid & 31, lane = tid >> 5;
    for (int grp = 0; grp < 4; grp++) {
        int tl = lane * 32 + grp * 8;
        float acc[8];
        #pragma unroll
        for (int u = 0; u < 8; u++) acc[u] = bsh[c];
        #pragma unroll
        for (int k = 0; k < KFILT; k++) {
            float wv = wsh[k * 32 + c];
            #pragma unroll
            for (int u = 0; u < 8; u++) acc[u] += wv * xsh[tl + u + k];
        }
        #pragma unroll
        for (int u = 0; u < 8; u++) {
            int t = t0 + tl + u;
            if (t < L0) {
                __half h, l;
                split_h(acc[u], h, l);
                oh[(size_t)t * 32 + c] = h;
                ol[(size_t)t * 32 + c] = l;
            }
        }
    }
}

// ---------------- one layer pass over a staged 384-row tile ----------------
template<int D>
static __device__ __forceinline__ void layer_pass(
    char* smem, uint32_t sb,
    uint32_t IXH, uint32_t IXL, uint32_t SGH, uint32_t SGL, uint32_t BLOB,
    __half* __restrict__ Gh, __half* __restrict__ Gl,
    int t0, int cut, int rowLim,
    __half* __restrict__ xouth, __half* __restrict__ xoutl, int L_out)
{
    const int tid = threadIdx.x;
    const int l    = tid & 31;
    const int w    = tid >> 5;
    const int grp  = l >> 3, mrow = l & 7;
    const int tw   = w * 32;
    const float* bia = (const float*)(smem + BLOB + 28672);

    float acc[4][4][4];
    #pragma unroll
    for (int mi = 0; mi < 4; mi++) {
        float b0 = bia[mi * 16 + (l >> 2)];
        float b8 = bia[mi * 16 + (l >> 2) + 8];
        #pragma unroll
        for (int ni = 0; ni < 4; ni++) {
            acc[mi][ni][0] = b0; acc[mi][ni][1] = b0;
            acc[mi][ni][2] = b8; acc[mi][ni][3] = b8;
        }
    }

    #pragma unroll
    for (int j = 0; j < 3; j++) {
        #pragma unroll
        for (int kc = 0; kc < 2; kc++) {
            uint32_t a4[4][4], b1[4][2];
            #pragma unroll
            for (int h2 = 0; h2 < 2; h2++) {
                int t = tw + j * D + h2 * 16 + ((grp >> 1) << 3) + mrow;
                int q = kc * 2 + (grp & 1);
                uint32_t R[4];
                LDM4(R, sb + IXH + sw(t, q));
                b1[h2 * 2][0] = R[0]; b1[h2 * 2][1] = R[1];
                b1[h2 * 2 + 1][0] = R[2]; b1[h2 * 2 + 1][1] = R[3];
            }
            int tm = ((grp & 1) << 3) + mrow;
            int qa = kc * 2 + (grp >> 1);
            #pragma unroll
            for (int mi = 0; mi < 4; mi++)
                LDM4(a4[mi], sb + BLOB + j * 4096 + sw(mi * 16 + tm, qa));
            #pragma unroll
            for (int mi = 0; mi < 4; mi++)
                #pragma unroll
                for (int ni = 0; ni < 4; ni++)
                    MMA16816(acc[mi][ni], a4[mi], b1[ni]);
            #pragma unroll
            for (int mi = 0; mi < 4; mi++)
                LDM4(a4[mi], sb + BLOB + 12288 + j * 4096 + sw(mi * 16 + tm, qa));
            #pragma unroll
            for (int mi = 0; mi < 4; mi++)
                #pragma unroll
                for (int ni = 0; ni < 4; ni++)
                    MMA16816(acc[mi][ni], a4[mi], b1[ni]);
        }
    }

    #pragma unroll
    for (int mi = 0; mi < 2; mi++)
        #pragma unroll
        for (int ni = 0; ni < 4; ni++)
            #pragma unroll
            for (int jj = 0; jj < 4; jj++) {
                float a1 = fminf(fmaxf(acc[mi][ni][jj], -30.f), 30.f);
                float a2 = fminf(fmaxf(acc[mi + 2][ni][jj], -30.f), 30.f);
                float u  = 1.f + __expf(-2.f * a1);
                float vv = 1.f + __expf(-a2);
                float gv = __fdividef(2.f - u, u * vv);
                int t_loc = tw + ni * 8 + 2 * (l & 3) + (jj & 1);
                int c     = mi * 16 + (l >> 2) + ((jj >= 2) ? 8 : 0);
                __half h, lo2;
                split_h(gv, h, lo2);
                uint32_t off = sw(t_loc, c >> 3) + (c & 7) * 2;
                *(__half*)(smem + SGH + off) = h;
                *(__half*)(smem + SGL + off) = lo2;
            }
    __syncwarp();

    {
        int row = tw + l;
        int uo  = t0 + row - cut;
        if (row < rowLim && uo >= 0 && uo < FINAL) {
            char* dh = (char*)(Gh + (size_t)uo * KPAD);
            char* dl = (char*)(Gl + (size_t)uo * KPAD);
            #pragma unroll
            for (int q = 0; q < 4; q++) {
                *(uint4*)(dh + q * 16) = *(uint4*)(smem + SGH + sw(row, q));
                *(uint4*)(dl + q * 16) = *(uint4*)(smem + SGL + sw(row, q));
            }
        }
    }

    float dacc[2][4][4];
    uint32_t hacc[2][4][2];
    #pragma unroll
    for (int mi = 0; mi < 2; mi++) {
        float b0 = bia[64 + mi * 16 + (l >> 2)];
        float b8 = bia[64 + mi * 16 + (l >> 2) + 8];
        #pragma unroll
        for (int ni = 0; ni < 4; ni++) {
            dacc[mi][ni][0] = b0; dacc[mi][ni][1] = b0;
            dacc[mi][ni][2] = b8; dacc[mi][ni][3] = b8;
            hacc[mi][ni][0] = 0u; hacc[mi][ni][1] = 0u;
        }
    }
    #pragma unroll
    for (int kc = 0; kc < 2; kc++) {
        uint32_t a4[2][4], b1[4][2], b2[4][2];
        #pragma unroll
        for (int h2 = 0; h2 < 2; h2++) {
            int t = tw + h2 * 16 + ((grp >> 1) << 3) + mrow;
            int q = kc * 2 + (grp & 1);
            uint32_t R[4];
            LDM4(R, sb + SGH + sw(t, q));
            b1[h2 * 2][0] = R[0]; b1[h2 * 2][1] = R[1];
            b1[h2 * 2 + 1][0] = R[2]; b1[h2 * 2 + 1][1] = R[3];
            LDM4(R, sb + SGL + sw(t, q));
            b2[h2 * 2][0] = R[0]; b2[h2 * 2][1] = R[1];
            b2[h2 * 2 + 1][0] = R[2]; b2[h2 * 2 + 1][1] = R[3];
        }
        int tm = ((grp & 1) << 3) + mrow;
        int qa = kc * 2 + (grp >> 1);
        #pragma unroll
        for (int mi = 0; mi < 2; mi++)
            LDM4(a4[mi], sb + BLOB + 24576 + sw(mi * 16 + tm, qa));
        #pragma unroll
        for (int mi = 0; mi < 2; mi++)
            #pragma unroll
            for (int ni = 0; ni < 4; ni++) {
                MMA16816(dacc[mi][ni], a4[mi], b1[ni]);
                MMA16816H(hacc[mi][ni], a4[mi], b2[ni]);
            }
        #pragma unroll
        for (int mi = 0; mi < 2; mi++)
            LDM4(a4[mi], sb + BLOB + 26624 + sw(mi * 16 + tm, qa));
        #pragma unroll
        for (int mi = 0; mi < 2; mi++)
            #pragma unroll
            for (int ni = 0; ni < 4; ni++)
                MMA16816H(hacc[mi][ni], a4[mi], b1[ni]);
    }
    __syncwarp();

    #pragma unroll
    for (int mi = 0; mi < 2; mi++)
        #pragma unroll
        for (int ni = 0; ni < 4; ni++) {
            __half2 h01 = *(__half2*)&hacc[mi][ni][0];
            __half2 h23 = *(__half2*)&hacc[mi][ni][1];
            float cr[4] = {__low2float(h01), __high2float(h01),
                           __low2float(h23), __high2float(h23)};
            #pragma unroll
            for (int jj = 0; jj < 4; jj++) {
                int t_loc = tw + ni * 8 + 2 * (l & 3) + (jj & 1);
                int c     = mi * 16 + (l >> 2) + ((jj >= 2) ? 8 : 0);
                uint32_t offx = sw(t_loc + D, c >> 3) + (c & 7) * 2;
                float xv = __half2float(*(__half*)(smem + IXH + offx))
                         + __half2float(*(__half*)(smem + IXL + offx));
                float ov = dacc[mi][ni][jj] + cr[jj] + xv;
                __half h, lo2;
                split_h(ov, h, lo2);
                uint32_t off = sw(t_loc, c >> 3) + (c & 7) * 2;
                *(__half*)(smem + SGH + off) = h;
                *(__half*)(smem + SGL + off) = lo2;
            }
        }
    __syncwarp();

    if (xouth) {
        int row = tw + l;
        int t   = t0 + row;
        if (row < rowLim && t < L_out) {
            char* dh = (char*)(xouth + (size_t)t * 32);
            char* dl = (char*)(xoutl + (size_t)t * 32);
            #pragma unroll
            for (int q = 0; q < 4; q++) {
                *(uint4*)(dh + q * 16) = *(uint4*)(smem + SGH + sw(row, q));
                *(uint4*)(dl + q * 16) = *(uint4*)(smem + SGL + sw(row, q));
            }
        }
    }
}

// ---------------- single-layer kernel --------------------------------------
template<int D>
__global__ __launch_bounds__(384, 1) void layer_mma(
    const __half* __restrict__ xinh, const __half* __restrict__ xinl,
    __half* __restrict__ xouth, __half* __restrict__ xoutl,
    const char* __restrict__ wblob,
    __half* __restrict__ Gh, __half* __restrict__ Gl,
    int L_in, int L_out, int cut)
{
    constexpr int RT = 384 + 2 * D;
    constexpr int XH  = 0;
    constexpr int XL  = RT * 64;
    constexpr int BL  = 2 * RT * 64;
    constexpr int STH = BL + WBLOB;
    constexpr int STL = STH + 24576;

    extern __shared__ char smem[];
    const uint32_t sb = smem_u32(smem);
    const int tid = threadIdx.x;
    const int t0  = blockIdx.x * 384;

    for (int idx = tid; idx < WBLOB / 16; idx += 384)
        CPASYNC16(sb + BL + idx * 16, wblob + idx * 16);

    for (int idx = tid; idx < RT * 4; idx += 384) {
        int t = idx >> 2, q = idx & 3;
        uint32_t so = sw(t, q);
        if (t0 + t < L_in) {
            CPASYNC16(sb + XH + so, xinh + (size_t)(t0 + t) * 32 + q * 8);
            CPASYNC16(sb + XL + so, xinl + (size_t)(t0 + t) * 32 + q * 8);
        } else {
            uint4 z = make_uint4(0, 0, 0, 0);
            *(uint4*)(smem + XH + so) = z;
            *(uint4*)(smem + XL + so) = z;
        }
    }
    asm volatile("cp.async.commit_group;" ::: "memory");
    asm volatile("cp.async.wait_group 0;" ::: "memory");
    __syncthreads();

    layer_pass<D>(smem, sb, XH, XL, STH, STL, BL, Gh, Gl,
                  t0, cut, 384, xouth, xoutl, L_out);
}

#define LAYER_SMEM_B(D_) (2 * (384 + 2 * (D_)) * 64 + WBLOB + 384 * 64 * 2)

// ---------------- fused two-layer kernel (dilations D1, D2=2*D1) -----------
template<int D1, int D2>
__global__ __launch_bounds__(384, 1) void layer2_mma(
    const __half* __restrict__ xinh, const __half* __restrict__ xinl,
    __half* __restrict__ xouth, __half* __restrict__ xoutl,
    const char* __restrict__ wblob,
    __half* __restrict__ Gh, __half* __restrict__ Gl,
    int L_in, int L_out2, int cut1, int cut2)
{
    constexpr int RT1  = 384 + 2 * D1;
    constexpr int SRT  = 384 + 2 * D2;
    constexpr int SOUT = 384 - 2 * D2;
    constexpr int XH  = 0;
    constexpr int XL  = RT1 * 64;
    constexpr int BL  = 2 * RT1 * 64;
    constexpr int STH = BL + 2 * WBLOB;
    constexpr int STL = STH + SRT * 64;

    extern __shared__ char smem[];
    const uint32_t sb = smem_u32(smem);
    const int tid = threadIdx.x;
    const int t0  = blockIdx.x * SOUT;

    for (int idx = tid; idx < 2 * WBLOB / 16; idx += 384)
        CPASYNC16(sb + BL + idx * 16, wblob + idx * 16);

    for (int idx = tid; idx < RT1 * 4; idx += 384) {
        int t = idx >> 2, q = idx & 3;
        uint32_t so = sw(t, q);
        if (t0 + t < L_in) {
            CPASYNC16(sb + XH + so, xinh + (size_t)(t0 + t) * 32 + q * 8);
            CPASYNC16(sb + XL + so, xinl + (size_t)(t0 + t) * 32 + q * 8);
        } else {
            uint4 z = make_uint4(0, 0, 0, 0);
            *(uint4*)(smem + XH + so) = z;
            *(uint4*)(smem + XL + so) = z;
        }
    }
    asm volatile("cp.async.commit_group;" ::: "memory");
    asm volatile("cp.async.wait_group 0;" ::: "memory");
    __syncthreads();

    layer_pass<D1>(smem, sb, XH, XL, STH, STL, BL, Gh, Gl,
                   t0, cut1, 384, (__half*)nullptr, (__half*)nullptr, 0);
    __syncthreads();
    layer_pass<D2>(smem, sb, STH, STL, XH, XL, BL + WBLOB, Gh + 32, Gl + 32,
                   t0, cut2, SOUT, xouth, xoutl, L_out2);
}

#define LAYER2_SMEM_B(D1_, D2_) (2 * (384 + 2 * (D1_)) * 64 + 2 * WBLOB \
                                 + 2 * (384 + 2 * (D2_)) * 64)

// ---------------- GEMM: 256 threads, 128x64 tile, 2 CTAs/SM ---------------
// Ah*(Bh+Bl): fp32 main + fp16-acc cross; 3-stage cp.async ring.
#define GSTG  32768
#define GSMEM (3 * GSTG)
__global__ __launch_bounds__(256, 2) void gemm_mma(
    const __half* __restrict__ Ah,
    const __half* __restrict__ Bh, const __half* __restrict__ Bl,
    const float* __restrict__ bias, int Kstr, int NC, int mode,
    __half* __restrict__ Ch, __half* __restrict__ Cl, int Cstr,
    float* __restrict__ Cf)
{
    extern __shared__ char smem[];
    const uint32_t sb = smem_u32(smem);
    const int tid = threadIdx.x;
    const int m0 = blockIdx.x << 7, n0 = blockIdx.y << 6;
    const int lane = tid & 31;
    const int wm = (tid >> 5) & 3, wn = tid >> 7;

    float acc[8][4];
    uint32_t hacc[8][2];
    #pragma unroll
    for (int i = 0; i < 8; i++) {
        #pragma unroll
        for (int j = 0; j < 4; j++) acc[i][j] = 0.f;
        hacc[i][0] = 0u; hacc[i][1] = 0u;
    }

    auto issue = [&](int c) {
        uint32_t buf = (uint32_t)(c % 3) * GSTG;
        int kc0 = c << 6;
        int rloc = tid >> 3, q = tid & 7;
        #pragma unroll
        for (int it = 0; it < 8; it++) {
            const __half* src;
            uint32_t dst;
            if (it < 4) {                       // A: 128 rows
                int rr = (it << 5) + rloc;
                src = Ah + (size_t)(m0 + rr) * Kstr + kc0 + q * 8;
                uint32_t off = (uint32_t)(rr * 128 + q * 16);
                off ^= (off >> 3) & 0x70;
                dst = sb + buf + off;
            } else if (it < 6) {                // Bh: 64 rows
                int rr = ((it - 4) << 5) + rloc;
                src = Bh + (size_t)(n0 + rr) * Kstr + kc0 + q * 8;
                uint32_t off = (uint32_t)(rr * 128 + q * 16);
                off ^= (off >> 3) & 0x70;
                dst = sb + buf + 16384u + off;
            } else {                            // Bl: 64 rows
                int rr = ((it - 6) << 5) + rloc;
                src = Bl + (size_t)(n0 + rr) * Kstr + kc0 + q * 8;
                uint32_t off = (uint32_t)(rr * 128 + q * 16);
                off ^= (off >> 3) & 0x70;
                dst = sb + buf + 24576u + off;
            }
            CPASYNC16(dst, src);
        }
        asm volatile("cp.async.commit_group;" ::: "memory");
    };

    issue(0);
    if (NC > 1) issue(1);
    for (int c = 0; c < NC; c++) {
        if (c + 1 < NC) {
            asm volatile("cp.async.wait_group 1;" ::: "memory");
        } else {
            asm volatile("cp.async.wait_group 0;" ::: "memory");
        }
        __syncthreads();
        if (c + 2 < NC) issue(c + 2);
        const uint32_t buf = sb + (uint32_t)(c % 3) * GSTG;

        #pragma unroll
        for (int ks = 0; ks < 4; ks++) {
            uint32_t ah[2][4], bh[4][2], bl2[4][2];
            #pragma unroll
            for (int mi = 0; mi < 2; mi++) {
                uint32_t row = wm * 32 + mi * 16 + (lane & 15);
                uint32_t ch  = ks * 2 + (lane >> 4);
                uint32_t off = row * 128 + ch * 16;
                off ^= (off >> 3) & 0x70;
                LDM4(ah[mi], buf + off);
            }
            #pragma unroll
            for (int nj = 0; nj < 2; nj++) {
                uint32_t row = wn * 32 + nj * 16 + (lane & 7) + ((lane >> 4) << 3);
                uint32_t ch  = ks * 2 + ((lane >> 3) & 1);
                uint32_t off = row * 128 + ch * 16;
                off ^= (off >> 3) & 0x70;
                uint32_t r4[4];
                LDM4(r4, buf + 16384u + off);
                bh[nj * 2][0] = r4[0]; bh[nj * 2][1] = r4[1];
                bh[nj * 2 + 1][0] = r4[2]; bh[nj * 2 + 1][1] = r4[3];
                LDM4(r4, buf + 24576u + off);
                bl2[nj * 2][0] = r4[0]; bl2[nj * 2][1] = r4[1];
                bl2[nj * 2 + 1][0] = r4[2]; bl2[nj * 2 + 1][1] = r4[3];
            }
            #pragma unroll
            for (int mi = 0; mi < 2; mi++)
                #pragma unroll
                for (int nt = 0; nt < 4; nt++) {
                    float*    C = acc[mi * 4 + nt];
                    uint32_t* H = hacc[mi * 4 + nt];
                    MMA16816(C, ah[mi], bh[nt]);
                    MMA16816H(H, ah[mi], bl2[nt]);
                }
        }
    }
    __syncthreads();

    float* cs = (float*)smem;
    #pragma unroll
    for (int mi = 0; mi < 2; mi++)
        #pragma unroll
        for (int nt = 0; nt < 4; nt++) {
            float*    C = acc[mi * 4 + nt];
            uint32_t* H = hacc[mi * 4 + nt];
            __half2 h01 = *(__half2*)&H[0];
            __half2 h23 = *(__half2*)&H[1];
            int mrow = wm * 32 + mi * 16 + (lane >> 2);
            int ncol = wn * 32 + nt * 8 + 2 * (lane & 3);
            cs[ncol * 132 + mrow]           = C[0] + __low2float(h01);
            cs[(ncol + 1) * 132 + mrow]     = C[1] + __high2float(h01);
            cs[ncol * 132 + mrow + 8]       = C[2] + __low2float(h23);
            cs[(ncol + 1) * 132 + mrow + 8] = C[3] + __high2float(h23);
        }
    __syncthreads();

    if (mode) {
        #pragma unroll
        for (int it = 0; it < 16; it++) {
            int idx = it * 256 + tid;
            int n = idx >> 6, mp = idx & 63;
            float2 v2 = *(float2*)&cs[n * 132 + 2 * mp];
            float b0 = __ldg(bias + m0 + 2 * mp);
            float b1 = __ldg(bias + m0 + 2 * mp + 1);
            float v0 = fmaxf(v2.x + b0, 0.f);
            float v1 = fmaxf(v2.y + b1, 0.f);
            __half h0, l0, h1, l1;
            split_h(v0, h0, l0);
            split_h(v1, h1, l1);
            uint32_t ph = (uint32_t)__half_as_ushort(h0) |
                          ((uint32_t)__half_as_ushort(h1) << 16);
            uint32_t pl = (uint32_t)__half_as_ushort(l0) |
                          ((uint32_t)__half_as_ushort(l1) << 16);
            size_t o = (size_t)(n0 + n) * Cstr + m0 + 2 * mp;
            *(uint32_t*)(Ch + o) = ph;
            *(uint32_t*)(Cl + o) = pl;
        }
    } else {
        #pragma unroll
        for (int it = 0; it < 32; it++) {
            int idx = it * 256 + tid;
            int n = idx & 63, m = idx >> 6;
            float v = cs[n * 132 + m] + __ldg(bias + m0 + m);
            Cf[(size_t)(m0 + m) * FINAL + n0 + n] = v;
        }
    }
}

// ---------------- launch --------------------------------------------------
extern "C" void kernel_launch(void* const* d_in, const int* in_sizes, int n_in,
                              void* d_out, int out_size)
{
    const float* x        = (const float*)d_in[0];
    const float* w_causal = (const float*)d_in[1];
    const float* b_causal = (const float*)d_in[2];
    const float* w_tanh   = (const float*)d_in[3];
    const float* b_tanh   = (const float*)d_in[4];
    const float* w_sig    = (const float*)d_in[5];
    const float* b_sig    = (const float*)d_in[6];
    const float* w_skip   = (const float*)d_in[7];
    const float* b_skip   = (const float*)d_in[8];
    const float* w_dense  = (const float*)d_in[9];
    const float* b_dense  = (const float*)d_in[10];
    const float* w_post1  = (const float*)d_in[11];
    const float* b_post1  = (const float*)d_in[12];
    const float* w_post2  = (const float*)d_in[13];
    const float* b_post2  = (const float*)d_in[14];

    float *bsum;
    __half *xah, *xal, *xbh, *xbl;
    __half *Ghi, *Glo, *Shi, *Slo, *Hhi, *Hlo;
    __half *WaH, *P1H, *P2H;
    char* wblob;
    cudaGetSymbolAddress((void**)&xah, g_xah);
    cudaGetSymbolAddress((void**)&xal, g_xal);
    cudaGetSymbolAddress((void**)&xbh, g_xbh);
    cudaGetSymbolAddress((void**)&xbl, g_xbl);
    cudaGetSymbolAddress((void**)&Ghi, g_Ghi);
    cudaGetSymbolAddress((void**)&Glo, g_Glo);
    cudaGetSymbolAddress((void**)&Shi, g_Shi);
    cudaGetSymbolAddress((void**)&Slo, g_Slo);
    cudaGetSymbolAddress((void**)&Hhi, g_Hhi);
    cudaGetSymbolAddress((void**)&Hlo, g_Hlo);
    cudaGetSymbolAddress((void**)&WaH, g_WaH);
    cudaGetSymbolAddress((void**)&P1H, g_P1H);
    cudaGetSymbolAddress((void**)&P2H, g_P2H);
    cudaGetSymbolAddress((void**)&bsum, g_bsum);
    cudaGetSymbolAddress((void**)&wblob, g_wblob);

    cudaFuncSetAttribute(gemm_mma,
                         cudaFuncAttributeMaxDynamicSharedMemorySize, GSMEM);

    prep_kernel<<<(SDIM * KPAD + 255) / 256, 256>>>(w_skip, b_skip, w_post1, w_post2);
    prep2_kernel<<<NL, 384>>>(w_tanh, b_tanh, w_sig, b_sig, w_dense, b_dense);
    causal_kernel<<<(L0 + 255) / 256, 256>>>(x, w_causal, b_causal, xah, xal);

    __half *curh = xah, *curl = xal, *nxth = xbh, *nxtl = xbl;
    int L = L0;
    int i = 0;
    while (i < NL) {
        int k = i % 9;
        int d = 1 << k;
        bool fuse = (i + 1 < NL) && (k == 0 || k == 2 || k == 4);
        if (fuse) {
            int d2   = d * 2;
            int Lmid = L - 2 * d;
            int Lout2 = Lmid - 2 * d2;
            int cut1 = (Lmid - FINAL) / 2;
            int cut2 = (Lout2 - FINAL) / 2;
            int SOUT = 384 - 2 * d2;

            void (*kfn)(const __half*, const __half*, __half*, __half*,
                        const char*, __half*, __half*, int, int, int, int) = nullptr;
            size_t smem = 0;
            switch (d) {
                case 1:  kfn = layer2_mma<1, 2>;   smem = LAYER2_SMEM_B(1, 2);   break;
                case 4:  kfn = layer2_mma<4, 8>;   smem = LAYER2_SMEM_B(4, 8);   break;
                case 16: kfn = layer2_mma<16, 32>; smem = LAYER2_SMEM_B(16, 32); break;
            }
            cudaFuncSetAttribute(kfn, cudaFuncAttributeMaxDynamicSharedMemorySize,
                                 (int)smem);
            kfn<<<(Lout2 + SOUT - 1) / SOUT, 384, smem>>>(
                curh, curl, nxth, nxtl,
                wblob + (size_t)i * WBLOB,
                Ghi + i * 32, Glo + i * 32,
                L, Lout2, cut1, cut2);
            L = Lout2;
            i += 2;
        } else {
            int Lout = L - 2 * d;
            int cut  = (Lout - FINAL) / 2;
            void (*kfn)(const __half*, const __half*, __half*, __half*,
                        const char*, __half*, __half*, int, int, int) = nullptr;
            size_t smem = 0;
            switch (d) {
                case 1:   kfn = layer_mma<1>;   smem = LAYER_SMEM_B(1);   break;
                case 2:   kfn = layer_mma<2>;   smem = LAYER_SMEM_B(2);   break;
                case 4:   kfn = layer_mma<4>;   smem = LAYER_SMEM_B(4);   break;
                case 8:   kfn = layer_mma<8>;   smem = LAYER_SMEM_B(8);   break;
                case 16:  kfn = layer_mma<16>;  smem = LAYER_SMEM_B(16);  break;
                case 32:  kfn = layer_mma<32>;  smem = LAYER_SMEM_B(32);  break;
                case 64:  kfn = layer_mma<64>;  smem = LAYER_SMEM_B(64);  break;
                case 128: kfn = layer_mma<128>; smem = LAYER_SMEM_B(128); break;
                case 256: kfn = layer_mma<256>; smem = LAYER_SMEM_B(256); break;
            }
            cudaFuncSetAttribute(kfn, cudaFuncAttributeMaxDynamicSharedMemorySize,
                                 (int)smem);
            kfn<<<(Lout + 383) / 384, 384, smem>>>(
                curh, curl, nxth, nxtl,
                wblob + (size_t)i * WBLOB,
                Ghi + i * 32, Glo + i * 32,
                L, Lout, cut);
            L = Lout;
            i += 1;
        }
        __half* t;
        t = curh; curh = nxth; nxth = t;
        t = curl; curl = nxtl; nxtl = t;
    }

    // skip GEMM: S = relu(Wa @ G + bsum)   M=512, K=1472, N=160000
    gemm_mma<<<dim3(SDIM / 128, FINAL / 64), 256, GSMEM>>>(
        WaH, Ghi, Glo, bsum, KPAD, KPAD / 64, 1, Shi, Slo, SDIM, nullptr);
    // post1: H = relu(W1 @ S + b1)         M=512, K=512
    gemm_mma<<<dim3(SDIM / 128, FINAL / 64), 256, GSMEM>>>(
        P1H, Shi, Slo, b_post1, SDIM, SDIM / 64, 1, Hhi, Hlo, SDIM, nullptr);
    // post2: out = W2 @ H + b2             M=256, K=512, fp32 channel-major
    gemm_mma<<<dim3(QDIM / 128, FINAL / 64), 256, GSMEM>>>(
        P2H, Hhi, Hlo, b_post2, SDIM, SDIM / 64, 0, nullptr, nullptr, 0,
        (float*)d_out);
}

// round 16
// speedup vs baseline: 1.5132x; 1.2252x over previous
#include <cuda_runtime.h>
#include <cuda_fp16.h>
#include <cstdint>

#define L_INPUT 165142
#define KFILT   33
#define L0      (L_INPUT - KFILT + 1)   /* 165110 */
#define RDC     32
#define SDIM    512
#define QDIM    256
#define NL      45
#define FINAL   160000
#define KPAD    1472                    /* 45*32=1440 padded to 64-multiple */
#define WBLOB   29056                   /* per-layer packed weights bytes */

// ---------------- scratch (static device globals; no allocation allowed) ----
__device__ __half g_xah[(size_t)L0 * 32];
__device__ __half g_xal[(size_t)L0 * 32];
__device__ __half g_xbh[(size_t)L0 * 32];
__device__ __half g_xbl[(size_t)L0 * 32];
__device__ __half g_Ghi[(size_t)FINAL * KPAD];
__device__ __half g_Shi[(size_t)FINAL * SDIM];
__device__ __half g_Slo[(size_t)FINAL * SDIM];
__device__ __half g_Hhi[(size_t)FINAL * SDIM];
__device__ __half g_Hlo[(size_t)FINAL * SDIM];
__device__ __half g_WaH[SDIM * KPAD];
__device__ __half g_P1H[SDIM * SDIM];
__device__ __half g_P2H[QDIM * SDIM];
__device__ float g_bsum[SDIM];
__device__ __align__(16) char g_wblob[(size_t)NL * WBLOB];

// ---------------- helpers --------------------------------------------------
static __device__ __forceinline__ uint32_t smem_u32(const void* p) {
    uint32_t a;
    asm("{ .reg .u64 t; cvta.to.shared.u64 t, %1; cvt.u32.u64 %0, t; }"
        : "=r"(a) : "l"(p));
    return a;
}
static __device__ __forceinline__ void split_h(float v, __half& h, __half& l) {
    h = __float2half(v);
    l = __float2half(v - __half2float(h));
}
static __device__ __forceinline__ uint32_t sw(int t, int q) {
    return (uint32_t)((t << 6) + (((q ^ ((t >> 1) & 3))) << 4));
}

#define LDM4(R, a) \
    asm volatile("ldmatrix.sync.aligned.m8n8.x4.shared.b16 {%0,%1,%2,%3}, [%4];" \
        : "=r"((R)[0]), "=r"((R)[1]), "=r"((R)[2]), "=r"((R)[3]) : "r"(a))

#define MMA16816(C, A, B) \
    asm volatile("mma.sync.aligned.m16n8k16.row.col.f32.f16.f16.f32 " \
        "{%0,%1,%2,%3}, {%4,%5,%6,%7}, {%8,%9}, {%0,%1,%2,%3};" \
        : "+f"((C)[0]), "+f"((C)[1]), "+f"((C)[2]), "+f"((C)[3]) \
        : "r"((A)[0]), "r"((A)[1]), "r"((A)[2]), "r"((A)[3]), \
          "r"((B)[0]), "r"((B)[1]))

#define MMA16816H(C, A, B) \
    asm volatile("mma.sync.aligned.m16n8k16.row.col.f16.f16.f16.f16 " \
        "{%0,%1}, {%2,%3,%4,%5}, {%6,%7}, {%0,%1};" \
        : "+r"((C)[0]), "+r"((C)[1]) \
        : "r"((A)[0]), "r"((A)[1]), "r"((A)[2]), "r"((A)[3]), \
          "r"((B)[0]), "r"((B)[1]))

#define CPASYNC16(dst, src) \
    asm volatile("cp.async.cg.shared.global [%0], [%1], 16;" \
        :: "r"(dst), "l"(src) : "memory")

// ---------------- prep: weights (hi) for big GEMMs, sum skip bias ---------
__global__ __launch_bounds__(256) void prep_kernel(const float* __restrict__ wskip,
                                                   const float* __restrict__ bskip,
                                                   const float* __restrict__ wp1,
                                                   const float* __restrict__ wp2)
{
    int idx = blockIdx.x * 256 + threadIdx.x;
    if (idx < SDIM * KPAD) {
        int c = idx / KPAD, k = idx - c * KPAD;
        float v = 0.f;
        if (k < NL * RDC) {
            int i = k >> 5, r = k & 31;
            v = wskip[(size_t)i * SDIM * RDC + (size_t)c * RDC + r];
        }
        g_WaH[idx] = __float2half(v);
    }
    if (idx < SDIM * SDIM) g_P1H[idx] = __float2half(wp1[idx]);
    if (idx < QDIM * SDIM) g_P2H[idx] = __float2half(wp2[idx]);
    if (idx < SDIM) {
        float s = 0.f;
        #pragma unroll
        for (int i = 0; i < NL; i++) s += bskip[i * SDIM + idx];
        g_bsum[idx] = s;
    }
}

// ---------------- prep2: pack per-layer weights into swizzled blobs -------
__global__ __launch_bounds__(384) void prep2_kernel(const float* __restrict__ wt,
                                                    const float* __restrict__ bt,
                                                    const float* __restrict__ ws,
                                                    const float* __restrict__ bs,
                                                    const float* __restrict__ wd,
                                                    const float* __restrict__ bd)
{
    const int i = blockIdx.x;
    char* blob = g_wblob + (size_t)i * WBLOB;
    const float* wti = wt + (size_t)i * 3072;
    const float* wsi = ws + (size_t)i * 3072;
    const float* wdi = wd + (size_t)i * 1024;
    int tid = threadIdx.x;

    for (int idx = tid; idx < 6144; idx += 384) {
        int m = idx / 96, rem = idx - m * 96, r = rem / 3, j = rem - r * 3;
        float v = (m < 32) ? wti[m * 96 + r * 3 + j] : wsi[(m - 32) * 96 + r * 3 + j];
        __half h, l;
        split_h(v, h, l);
        uint32_t off = (uint32_t)(j * 4096) + sw(m, r >> 3) + (r & 7) * 2;
        *(__half*)(blob + off)         = h;
        *(__half*)(blob + 12288 + off) = l;
    }
    for (int idx = tid; idx < 1024; idx += 384) {
        int c = idx >> 5, r = idx & 31;
        __half h, l;
        split_h(wdi[idx], h, l);
        uint32_t off = sw(c, r >> 3) + (r & 7) * 2;
        *(__half*)(blob + 24576 + off) = h;
        *(__half*)(blob + 26624 + off) = l;
    }
    if (tid < 32) {
        float* bia = (float*)(blob + 28672);
        bia[tid]      = bt[i * 32 + tid];
        bia[32 + tid] = bs[i * 32 + tid];
        bia[64 + tid] = bd[i * 32 + tid];
    }
}

// ---------------- causal conv: 1 -> 32 ch, K=33; out time-major hi/lo ------
__global__ __launch_bounds__(256) void causal_kernel(const float* __restrict__ x,
                                                     const float* __restrict__ w,
                                                     const float* __restrict__ b,
                                                     __half* __restrict__ oh,
                                                     __half* __restrict__ ol)
{
    __shared__ float xsh[256 + KFILT - 1];
    __shared__ float wsh[KFILT * 32];
    __shared__ float bsh[32];
    int tid = threadIdx.x;
    int t0  = blockIdx.x * 256;

    for (int i = tid; i < 256 + KFILT - 1; i += 256) {
        int g = t0 + i;
        xsh[i] = (g < L_INPUT) ? x[g] : 0.f;
    }
    for (int i = tid; i < 32 * KFILT; i += 256) {
        int c = i / KFILT, k = i - c * KFILT;
        wsh[k * 32 + c] = w[i];
    }
    if (tid < 32) bsh[tid] = b[tid];
    __syncthreads();

    int c = tid & 31, lane = tid >> 5;
    for (int grp = 0; grp < 4; grp++) {
        int tl = lane * 32 + grp * 8;
        float acc[8];
        #pragma unroll
        for (int u = 0; u < 8; u++) acc[u] = bsh[c];
        #pragma unroll
        for (int k = 0; k < KFILT; k++) {
            float wv = wsh[k * 32 + c];
            #pragma unroll
            for (int u = 0; u < 8; u++) acc[u] += wv * xsh[tl + u + k];
        }
        #pragma unroll
        for (int u = 0; u < 8; u++) {
            int t = t0 + tl + u;
            if (t < L0) {
                __half h, l;
                split_h(acc[u], h, l);
                oh[(size_t)t * 32 + c] = h;
                ol[(size_t)t * 32 + c] = l;
            }
        }
    }
}

// ---------------- one layer pass over a staged 384-row tile ----------------
template<int D>
static __device__ __forceinline__ void layer_pass(
    char* smem, uint32_t sb,
    uint32_t IXH, uint32_t IXL, uint32_t SGH, uint32_t SGL, uint32_t BLOB,
    __half* __restrict__ Gh,
    int t0, int cut, int rowLim,
    __half* __restrict__ xouth, __half* __restrict__ xoutl, int L_out)
{
    const int tid = threadIdx.x;
    const int l    = tid & 31;
    const int w    = tid >> 5;
    const int grp  = l >> 3, mrow = l & 7;
    const int tw   = w * 32;
    const float* bia = (const float*)(smem + BLOB + 28672);

    float acc[4][4][4];
    #pragma unroll
    for (int mi = 0; mi < 4; mi++) {
        float b0 = bia[mi * 16 + (l >> 2)];
        float b8 = bia[mi * 16 + (l >> 2) + 8];
        #pragma unroll
        for (int ni = 0; ni < 4; ni++) {
            acc[mi][ni][0] = b0; acc[mi][ni][1] = b0;
            acc[mi][ni][2] = b8; acc[mi][ni][3] = b8;
        }
    }

    #pragma unroll
    for (int j = 0; j < 3; j++) {
        #pragma unroll
        for (int kc = 0; kc < 2; kc++) {
            uint32_t a4[4][4], b1[4][2];
            #pragma unroll
            for (int h2 = 0; h2 < 2; h2++) {
                int t = tw + j * D + h2 * 16 + ((grp >> 1) << 3) + mrow;
                int q = kc * 2 + (grp & 1);
                uint32_t R[4];
                LDM4(R, sb + IXH + sw(t, q));
                b1[h2 * 2][0] = R[0]; b1[h2 * 2][1] = R[1];
                b1[h2 * 2 + 1][0] = R[2]; b1[h2 * 2 + 1][1] = R[3];
            }
            int tm = ((grp & 1) << 3) + mrow;
            int qa = kc * 2 + (grp >> 1);
            #pragma unroll
            for (int mi = 0; mi < 4; mi++)
                LDM4(a4[mi], sb + BLOB + j * 4096 + sw(mi * 16 + tm, qa));
            #pragma unroll
            for (int mi = 0; mi < 4; mi++)
                #pragma unroll
                for (int ni = 0; ni < 4; ni++)
                    MMA16816(acc[mi][ni], a4[mi], b1[ni]);
            #pragma unroll
            for (int mi = 0; mi < 4; mi++)
                LDM4(a4[mi], sb + BLOB + 12288 + j * 4096 + sw(mi * 16 + tm, qa));
            #pragma unroll
            for (int mi = 0; mi < 4; mi++)
                #pragma unroll
                for (int ni = 0; ni < 4; ni++)
                    MMA16816(acc[mi][ni], a4[mi], b1[ni]);
        }
    }

    #pragma unroll
    for (int mi = 0; mi < 2; mi++)
        #pragma unroll
        for (int ni = 0; ni < 4; ni++)
            #pragma unroll
            for (int jj = 0; jj < 4; jj++) {
                float a1 = fminf(fmaxf(acc[mi][ni][jj], -30.f), 30.f);
                float a2 = fminf(fmaxf(acc[mi + 2][ni][jj], -30.f), 30.f);
                float u  = 1.f + __expf(-2.f * a1);
                float vv = 1.f + __expf(-a2);
                float gv = __fdividef(2.f - u, u * vv);
                int t_loc = tw + ni * 8 + 2 * (l & 3) + (jj & 1);
                int c     = mi * 16 + (l >> 2) + ((jj >= 2) ? 8 : 0);
                __half h, lo2;
                split_h(gv, h, lo2);
                uint32_t off = sw(t_loc, c >> 3) + (c & 7) * 2;
                *(__half*)(smem + SGH + off) = h;
                *(__half*)(smem + SGL + off) = lo2;
            }
    __syncwarp();

    {
        int row = tw + l;
        int uo  = t0 + row - cut;
        if (row < rowLim && uo >= 0 && uo < FINAL) {
            char* dh = (char*)(Gh + (size_t)uo * KPAD);
            #pragma unroll
            for (int q = 0; q < 4; q++)
                *(uint4*)(dh + q * 16) = *(uint4*)(smem + SGH + sw(row, q));
        }
    }

    float dacc[2][4][4];
    uint32_t hacc[2][4][2];
    #pragma unroll
    for (int mi = 0; mi < 2; mi++) {
        float b0 = bia[64 + mi * 16 + (l >> 2)];
        float b8 = bia[64 + mi * 16 + (l >> 2) + 8];
        #pragma unroll
        for (int ni = 0; ni < 4; ni++) {
            dacc[mi][ni][0] = b0; dacc[mi][ni][1] = b0;
            dacc[mi][ni][2] = b8; dacc[mi][ni][3] = b8;
            hacc[mi][ni][0] = 0u; hacc[mi][ni][1] = 0u;
        }
    }
    #pragma unroll
    for (int kc = 0; kc < 2; kc++) {
        uint32_t a4[2][4], b1[4][2], b2[4][2];
        #pragma unroll
        for (int h2 = 0; h2 < 2; h2++) {
            int t = tw + h2 * 16 + ((grp >> 1) << 3) + mrow;
            int q = kc * 2 + (grp & 1);
            uint32_t R[4];
            LDM4(R, sb + SGH + sw(t, q));
            b1[h2 * 2][0] = R[0]; b1[h2 * 2][1] = R[1];
            b1[h2 * 2 + 1][0] = R[2]; b1[h2 * 2 + 1][1] = R[3];
            LDM4(R, sb + SGL + sw(t, q));
            b2[h2 * 2][0] = R[0]; b2[h2 * 2][1] = R[1];
            b2[h2 * 2 + 1][0] = R[2]; b2[h2 * 2 + 1][1] = R[3];
        }
        int tm = ((grp & 1) << 3) + mrow;
        int qa = kc * 2 + (grp >> 1);
        #pragma unroll
        for (int mi = 0; mi < 2; mi++)
            LDM4(a4[mi], sb + BLOB + 24576 + sw(mi * 16 + tm, qa));
        #pragma unroll
        for (int mi = 0; mi < 2; mi++)
            #pragma unroll
            for (int ni = 0; ni < 4; ni++) {
                MMA16816(dacc[mi][ni], a4[mi], b1[ni]);
                MMA16816H(hacc[mi][ni], a4[mi], b2[ni]);
            }
        #pragma unroll
        for (int mi = 0; mi < 2; mi++)
            LDM4(a4[mi], sb + BLOB + 26624 + sw(mi * 16 + tm, qa));
        #pragma unroll
        for (int mi = 0; mi < 2; mi++)
            #pragma unroll
            for (int ni = 0; ni < 4; ni++)
                MMA16816H(hacc[mi][ni], a4[mi], b1[ni]);
    }
    __syncwarp();

    #pragma unroll
    for (int mi = 0; mi < 2; mi++)
        #pragma unroll
        for (int ni = 0; ni < 4; ni++) {
            __half2 h01 = *(__half2*)&hacc[mi][ni][0];
            __half2 h23 = *(__half2*)&hacc[mi][ni][1];
            float cr[4] = {__low2float(h01), __high2float(h01),
                           __low2float(h23), __high2float(h23)};
            #pragma unroll
            for (int jj = 0; jj < 4; jj++) {
                int t_loc = tw + ni * 8 + 2 * (l & 3) + (jj & 1);
                int c     = mi * 16 + (l >> 2) + ((jj >= 2) ? 8 : 0);
                uint32_t offx = sw(t_loc + D, c >> 3) + (c & 7) * 2;
                float xv = __half2float(*(__half*)(smem + IXH + offx))
                         + __half2float(*(__half*)(smem + IXL + offx));
                float ov = dacc[mi][ni][jj] + cr[jj] + xv;
                __half h, lo2;
                split_h(ov, h, lo2);
                uint32_t off = sw(t_loc, c >> 3) + (c & 7) * 2;
                *(__half*)(smem + SGH + off) = h;
                *(__half*)(smem + SGL + off) = lo2;
            }
        }
    __syncwarp();

    if (xouth) {
        int row = tw + l;
        int t   = t0 + row;
        if (row < rowLim && t < L_out) {
            char* dh = (char*)(xouth + (size_t)t * 32);
            char* dl = (char*)(xoutl + (size_t)t * 32);
            #pragma unroll
            for (int q = 0; q < 4; q++) {
                *(uint4*)(dh + q * 16) = *(uint4*)(smem + SGH + sw(row, q));
                *(uint4*)(dl + q * 16) = *(uint4*)(smem + SGL + sw(row, q));
            }
        }
    }
}

// ---------------- single-layer kernel --------------------------------------
template<int D>
__global__ __launch_bounds__(384, 1) void layer_mma(
    const __half* __restrict__ xinh, const __half* __restrict__ xinl,
    __half* __restrict__ xouth, __half* __restrict__ xoutl,
    const char* __restrict__ wblob,
    __half* __restrict__ Gh,
    int L_in, int L_out, int cut)
{
    constexpr int RT = 384 + 2 * D;
    constexpr int XH  = 0;
    constexpr int XL  = RT * 64;
    constexpr int BL  = 2 * RT * 64;
    constexpr int STH = BL + WBLOB;
    constexpr int STL = STH + 24576;

    extern __shared__ char smem[];
    const uint32_t sb = smem_u32(smem);
    const int tid = threadIdx.x;
    const int t0  = blockIdx.x * 384;

    for (int idx = tid; idx < WBLOB / 16; idx += 384)
        CPASYNC16(sb + BL + idx * 16, wblob + idx * 16);

    for (int idx = tid; idx < RT * 4; idx += 384) {
        int t = idx >> 2, q = idx & 3;
        uint32_t so = sw(t, q);
        if (t0 + t < L_in) {
            CPASYNC16(sb + XH + so, xinh + (size_t)(t0 + t) * 32 + q * 8);
            CPASYNC16(sb + XL + so, xinl + (size_t)(t0 + t) * 32 + q * 8);
        } else {
            uint4 z = make_uint4(0, 0, 0, 0);
            *(uint4*)(smem + XH + so) = z;
            *(uint4*)(smem + XL + so) = z;
        }
    }
    asm volatile("cp.async.commit_group;" ::: "memory");
    asm volatile("cp.async.wait_group 0;" ::: "memory");
    __syncthreads();

    layer_pass<D>(smem, sb, XH, XL, STH, STL, BL, Gh,
                  t0, cut, 384, xouth, xoutl, L_out);
}

#define LAYER_SMEM_B(D_) (2 * (384 + 2 * (D_)) * 64 + WBLOB + 384 * 64 * 2)

// ---------------- fused two-layer kernel (dilations D1, D2=2*D1) -----------
template<int D1, int D2>
__global__ __launch_bounds__(384, 1) void layer2_mma(
    const __half* __restrict__ xinh, const __half* __restrict__ xinl,
    __half* __restrict__ xouth, __half* __restrict__ xoutl,
    const char* __restrict__ wblob,
    __half* __restrict__ Gh,
    int L_in, int L_out2, int cut1, int cut2)
{
    constexpr int RT1  = 384 + 2 * D1;
    constexpr int SRT  = 384 + 2 * D2;
    constexpr int SOUT = 384 - 2 * D2;
    constexpr int XH  = 0;
    constexpr int XL  = RT1 * 64;
    constexpr int BL  = 2 * RT1 * 64;
    constexpr int STH = BL + 2 * WBLOB;
    constexpr int STL = STH + SRT * 64;

    extern __shared__ char smem[];
    const uint32_t sb = smem_u32(smem);
    const int tid = threadIdx.x;
    const int t0  = blockIdx.x * SOUT;

    for (int idx = tid; idx < 2 * WBLOB / 16; idx += 384)
        CPASYNC16(sb + BL + idx * 16, wblob + idx * 16);

    for (int idx = tid; idx < RT1 * 4; idx += 384) {
        int t = idx >> 2, q = idx & 3;
        uint32_t so = sw(t, q);
        if (t0 + t < L_in) {
            CPASYNC16(sb + XH + so, xinh + (size_t)(t0 + t) * 32 + q * 8);
            CPASYNC16(sb + XL + so, xinl + (size_t)(t0 + t) * 32 + q * 8);
        } else {
            uint4 z = make_uint4(0, 0, 0, 0);
            *(uint4*)(smem + XH + so) = z;
            *(uint4*)(smem + XL + so) = z;
        }
    }
    asm volatile("cp.async.commit_group;" ::: "memory");
    asm volatile("cp.async.wait_group 0;" ::: "memory");
    __syncthreads();

    layer_pass<D1>(smem, sb, XH, XL, STH, STL, BL, Gh,
                   t0, cut1, 384, (__half*)nullptr, (__half*)nullptr, 0);
    __syncthreads();
    layer_pass<D2>(smem, sb, STH, STL, XH, XL, BL + WBLOB, Gh + 32,
                   t0, cut2, SOUT, xouth, xoutl, L_out2);
}

#define LAYER2_SMEM_B(D1_, D2_) (2 * (384 + 2 * (D1_)) * 64 + 2 * WBLOB \
                                 + 2 * (384 + 2 * (D2_)) * 64)

// ---------------- GEMM: 256 threads, 128x64 tile, 2 CTAs/SM ---------------
// UBL=1: Ah*(Bh+Bl) fp32 main + fp16-acc cross. UBL=0: Ah*Bh only.
#define GSTG  32768
#define GSMEM (3 * GSTG)
template<int UBL>
__global__ __launch_bounds__(256, 2) void gemm_mma(
    const __half* __restrict__ Ah,
    const __half* __restrict__ Bh, const __half* __restrict__ Bl,
    const float* __restrict__ bias, int Kstr, int NC, int mode,
    __half* __restrict__ Ch, __half* __restrict__ Cl, int Cstr,
    float* __restrict__ Cf)
{
    extern __shared__ char smem[];
    const uint32_t sb = smem_u32(smem);
    const int tid = threadIdx.x;
    const int m0 = blockIdx.x << 7, n0 = blockIdx.y << 6;
    const int lane = tid & 31;
    const int wm = (tid >> 5) & 3, wn = tid >> 7;

    float acc[8][4];
    uint32_t hacc[8][2];
    #pragma unroll
    for (int i = 0; i < 8; i++) {
        #pragma unroll
        for (int j = 0; j < 4; j++) acc[i][j] = 0.f;
        hacc[i][0] = 0u; hacc[i][1] = 0u;
    }

    auto issue = [&](int c) {
        uint32_t buf = (uint32_t)(c % 3) * GSTG;
        int kc0 = c << 6;
        int rloc = tid >> 3, q = tid & 7;
        #pragma unroll
        for (int it = 0; it < (UBL ? 8 : 6); it++) {
            const __half* src;
            uint32_t dst;
            if (it < 4) {                       // A: 128 rows
                int rr = (it << 5) + rloc;
                src = Ah + (size_t)(m0 + rr) * Kstr + kc0 + q * 8;
                uint32_t off = (uint32_t)(rr * 128 + q * 16);
                off ^= (off >> 3) & 0x70;
                dst = sb + buf + off;
            } else if (it < 6) {                // Bh: 64 rows
                int rr = ((it - 4) << 5) + rloc;
                src = Bh + (size_t)(n0 + rr) * Kstr + kc0 + q * 8;
                uint32_t off = (uint32_t)(rr * 128 + q * 16);
                off ^= (off >> 3) & 0x70;
                dst = sb + buf + 16384u + off;
            } else {                            // Bl: 64 rows
                int rr = ((it - 6) << 5) + rloc;
                src = Bl + (size_t)(n0 + rr) * Kstr + kc0 + q * 8;
                uint32_t off = (uint32_t)(rr * 128 + q * 16);
                off ^= (off >> 3) & 0x70;
                dst = sb + buf + 24576u + off;
            }
            CPASYNC16(dst, src);
        }
        asm volatile("cp.async.commit_group;" ::: "memory");
    };

    issue(0);
    if (NC > 1) issue(1);
    for (int c = 0; c < NC; c++) {
        if (c + 1 < NC) {
            asm volatile("cp.async.wait_group 1;" ::: "memory");
        } else {
            asm volatile("cp.async.wait_group 0;" ::: "memory");
        }
        __syncthreads();
        if (c + 2 < NC) issue(c + 2);
        const uint32_t buf = sb + (uint32_t)(c % 3) * GSTG;

        #pragma unroll
        for (int ks = 0; ks < 4; ks++) {
            uint32_t ah[2][4], bh[4][2], bl2[4][2];
            #pragma unroll
            for (int mi = 0; mi < 2; mi++) {
                uint32_t row = wm * 32 + mi * 16 + (lane & 15);
                uint32_t ch  = ks * 2 + (lane >> 4);
                uint32_t off = row * 128 + ch * 16;
                off ^= (off >> 3) & 0x70;
                LDM4(ah[mi], buf + off);
            }
            #pragma unroll
            for (int nj = 0; nj < 2; nj++) {
                uint32_t row = wn * 32 + nj * 16 + (lane & 7) + ((lane >> 4) << 3);
                uint32_t ch  = ks * 2 + ((lane >> 3) & 1);
                uint32_t off = row * 128 + ch * 16;
                off ^= (off >> 3) & 0x70;
                uint32_t r4[4];
                LDM4(r4, buf + 16384u + off);
                bh[nj * 2][0] = r4[0]; bh[nj * 2][1] = r4[1];
                bh[nj * 2 + 1][0] = r4[2]; bh[nj * 2 + 1][1] = r4[3];
                if (UBL) {
                    LDM4(r4, buf + 24576u + off);
                    bl2[nj * 2][0] = r4[0]; bl2[nj * 2][1] = r4[1];
                    bl2[nj * 2 + 1][0] = r4[2]; bl2[nj * 2 + 1][1] = r4[3];
                }
            }
            #pragma unroll
            for (int mi = 0; mi < 2; mi++)
                #pragma unroll
                for (int nt = 0; nt < 4; nt++) {
                    float*    C = acc[mi * 4 + nt];
                    uint32_t* H = hacc[mi * 4 + nt];
                    MMA16816(C, ah[mi], bh[nt]);
                    if (UBL) MMA16816H(H, ah[mi], bl2[nt]);
                }
        }
    }
    __syncthreads();

    float* cs = (float*)smem;
    #pragma unroll
    for (int mi = 0; mi < 2; mi++)
        #pragma unroll
        for (int nt = 0; nt < 4; nt++) {
            float*    C = acc[mi * 4 + nt];
            uint32_t* H = hacc[mi * 4 + nt];
            __half2 h01 = *(__half2*)&H[0];
            __half2 h23 = *(__half2*)&H[1];
            int mrow = wm * 32 + mi * 16 + (lane >> 2);
            int ncol = wn * 32 + nt * 8 + 2 * (lane & 3);
            cs[ncol * 132 + mrow]           = C[0] + __low2float(h01);
            cs[(ncol + 1) * 132 + mrow]     = C[1] + __high2float(h01);
            cs[ncol * 132 + mrow + 8]       = C[2] + __low2float(h23);
            cs[(ncol + 1) * 132 + mrow + 8] = C[3] + __high2float(h23);
        }
    __syncthreads();

    if (mode) {
        #pragma unroll
        for (int it = 0; it < 16; it++) {
            int idx = it * 256 + tid;
            int n = idx >> 6, mp = idx & 63;
            float2 v2 = *(float2*)&cs[n * 132 + 2 * mp];
            float b0 = __ldg(bias + m0 + 2 * mp);
            float b1 = __ldg(bias + m0 + 2 * mp + 1);
            float v0 = fmaxf(v2.x + b0, 0.f);
            float v1 = fmaxf(v2.y + b1, 0.f);
            __half h0, l0, h1, l1;
            split_h(v0, h0, l0);
            split_h(v1, h1, l1);
            uint32_t ph = (uint32_t)__half_as_ushort(h0) |
                          ((uint32_t)__half_as_ushort(h1) << 16);
            uint32_t pl = (uint32_t)__half_as_ushort(l0) |
                          ((uint32_t)__half_as_ushort(l1) << 16);
            size_t o = (size_t)(n0 + n) * Cstr + m0 + 2 * mp;
            *(uint32_t*)(Ch + o) = ph;
            *(uint32_t*)(Cl + o) = pl;
        }
    } else {
        #pragma unroll
        for (int it = 0; it < 32; it++) {
            int idx = it * 256 + tid;
            int n = idx & 63, m = idx >> 6;
            float v = cs[n * 132 + m] + __ldg(bias + m0 + m);
            Cf[(size_t)(m0 + m) * FINAL + n0 + n] = v;
        }
    }
}

// ---------------- launch --------------------------------------------------
extern "C" void kernel_launch(void* const* d_in, const int* in_sizes, int n_in,
                              void* d_out, int out_size)
{
    const float* x        = (const float*)d_in[0];
    const float* w_causal = (const float*)d_in[1];
    const float* b_causal = (const float*)d_in[2];
    const float* w_tanh   = (const float*)d_in[3];
    const float* b_tanh   = (const float*)d_in[4];
    const float* w_sig    = (const float*)d_in[5];
    const float* b_sig    = (const float*)d_in[6];
    const float* w_skip   = (const float*)d_in[7];
    const float* b_skip   = (const float*)d_in[8];
    const float* w_dense  = (const float*)d_in[9];
    const float* b_dense  = (const float*)d_in[10];
    const float* w_post1  = (const float*)d_in[11];
    const float* b_post1  = (const float*)d_in[12];
    const float* w_post2  = (const float*)d_in[13];
    const float* b_post2  = (const float*)d_in[14];

    float *bsum;
    __half *xah, *xal, *xbh, *xbl;
    __half *Ghi, *Shi, *Slo, *Hhi, *Hlo;
    __half *WaH, *P1H, *P2H;
    char* wblob;
    cudaGetSymbolAddress((void**)&xah, g_xah);
    cudaGetSymbolAddress((void**)&xal, g_xal);
    cudaGetSymbolAddress((void**)&xbh, g_xbh);
    cudaGetSymbolAddress((void**)&xbl, g_xbl);
    cudaGetSymbolAddress((void**)&Ghi, g_Ghi);
    cudaGetSymbolAddress((void**)&Shi, g_Shi);
    cudaGetSymbolAddress((void**)&Slo, g_Slo);
    cudaGetSymbolAddress((void**)&Hhi, g_Hhi);
    cudaGetSymbolAddress((void**)&Hlo, g_Hlo);
    cudaGetSymbolAddress((void**)&WaH, g_WaH);
    cudaGetSymbolAddress((void**)&P1H, g_P1H);
    cudaGetSymbolAddress((void**)&P2H, g_P2H);
    cudaGetSymbolAddress((void**)&bsum, g_bsum);
    cudaGetSymbolAddress((void**)&wblob, g_wblob);

    cudaFuncSetAttribute(gemm_mma<0>,
                         cudaFuncAttributeMaxDynamicSharedMemorySize, GSMEM);
    cudaFuncSetAttribute(gemm_mma<1>,
                         cudaFuncAttributeMaxDynamicSharedMemorySize, GSMEM);

    prep_kernel<<<(SDIM * KPAD + 255) / 256, 256>>>(w_skip, b_skip, w_post1, w_post2);
    prep2_kernel<<<NL, 384>>>(w_tanh, b_tanh, w_sig, b_sig, w_dense, b_dense);
    causal_kernel<<<(L0 + 255) / 256, 256>>>(x, w_causal, b_causal, xah, xal);

    __half *curh = xah, *curl = xal, *nxth = xbh, *nxtl = xbl;
    int L = L0;
    int i = 0;
    while (i < NL) {
        int k = i % 9;
        int d = 1 << k;
        bool fuse = (i + 1 < NL) && (k == 0 || k == 2 || k == 4);
        if (fuse) {
            int d2   = d * 2;
            int Lmid = L - 2 * d;
            int Lout2 = Lmid - 2 * d2;
            int cut1 = (Lmid - FINAL) / 2;
            int cut2 = (Lout2 - FINAL) / 2;
            int SOUT = 384 - 2 * d2;

            void (*kfn)(const __half*, const __half*, __half*, __half*,
                        const char*, __half*, int, int, int, int) = nullptr;
            size_t smem = 0;
            switch (d) {
                case 1:  kfn = layer2_mma<1, 2>;   smem = LAYER2_SMEM_B(1, 2);   break;
                case 4:  kfn = layer2_mma<4, 8>;   smem = LAYER2_SMEM_B(4, 8);   break;
                case 16: kfn = layer2_mma<16, 32>; smem = LAYER2_SMEM_B(16, 32); break;
            }
            cudaFuncSetAttribute(kfn, cudaFuncAttributeMaxDynamicSharedMemorySize,
                                 (int)smem);
            kfn<<<(Lout2 + SOUT - 1) / SOUT, 384, smem>>>(
                curh, curl, nxth, nxtl,
                wblob + (size_t)i * WBLOB,
                Ghi + i * 32,
                L, Lout2, cut1, cut2);
            L = Lout2;
            i += 2;
        } else {
            int Lout = L - 2 * d;
            int cut  = (Lout - FINAL) / 2;
            void (*kfn)(const __half*, const __half*, __half*, __half*,
                        const char*, __half*, int, int, int) = nullptr;
            size_t smem = 0;
            switch (d) {
                case 1:   kfn = layer_mma<1>;   smem = LAYER_SMEM_B(1);   break;
                case 2:   kfn = layer_mma<2>;   smem = LAYER_SMEM_B(2);   break;
                case 4:   kfn = layer_mma<4>;   smem = LAYER_SMEM_B(4);   break;
                case 8:   kfn = layer_mma<8>;   smem = LAYER_SMEM_B(8);   break;
                case 16:  kfn = layer_mma<16>;  smem = LAYER_SMEM_B(16);  break;
                case 32:  kfn = layer_mma<32>;  smem = LAYER_SMEM_B(32);  break;
                case 64:  kfn = layer_mma<64>;  smem = LAYER_SMEM_B(64);  break;
                case 128: kfn = layer_mma<128>; smem = LAYER_SMEM_B(128); break;
                case 256: kfn = layer_mma<256>; smem = LAYER_SMEM_B(256); break;
            }
            cudaFuncSetAttribute(kfn, cudaFuncAttributeMaxDynamicSharedMemorySize,
                                 (int)smem);
            kfn<<<(Lout + 383) / 384, 384, smem>>>(
                curh, curl, nxth, nxtl,
                wblob + (size_t)i * WBLOB,
                Ghi + i * 32,
                L, Lout, cut);
            L = Lout;
            i += 1;
        }
        __half* t;
        t = curh; curh = nxth; nxth = t;
        t = curl; curl = nxtl; nxtl = t;
    }

    // skip GEMM: S = relu(Wa @ Ghi + bsum)   M=512, K=1472, N=160000 (no Bl)
    gemm_mma<0><<<dim3(SDIM / 128, FINAL / 64), 256, GSMEM>>>(
        WaH, Ghi, nullptr, bsum, KPAD, KPAD / 64, 1, Shi, Slo, SDIM, nullptr);
    // post1: H = relu(W1 @ S + b1)           M=512, K=512
    gemm_mma<1><<<dim3(SDIM / 128, FINAL / 64), 256, GSMEM>>>(
        P1H, Shi, Slo, b_post1, SDIM, SDIM / 64, 1, Hhi, Hlo, SDIM, nullptr);
    // post2: out = W2 @ H + b2               M=256, K=512, fp32 channel-major
    gemm_mma<1><<<dim3(QDIM / 128, FINAL / 64), 256, GSMEM>>>(
        P2H, Hhi, Hlo, b_post2, SDIM, SDIM / 64, 0, nullptr, nullptr, 0,
        (float*)d_out);
}

// round 17
// speedup vs baseline: 1.6679x; 1.1023x over previous
#include <cuda_runtime.h>
#include <cuda_fp16.h>
#include <cstdint>

#define L_INPUT 165142
#define KFILT   33
#define L0      (L_INPUT - KFILT + 1)   /* 165110 */
#define RDC     32
#define SDIM    512
#define QDIM    256
#define NL      45
#define FINAL   160000
#define KPAD    1472                    /* 45*32=1440 padded to 64-multiple */
#define WBLOB   29056                   /* per-layer packed weights bytes */

// ---------------- scratch (static device globals; no allocation allowed) ----
__device__ __half g_xah[(size_t)L0 * 32];
__device__ __half g_xal[(size_t)L0 * 32];
__device__ __half g_xbh[(size_t)L0 * 32];
__device__ __half g_xbl[(size_t)L0 * 32];
__device__ __half g_Ghi[(size_t)FINAL * KPAD];
__device__ __half g_Shi[(size_t)FINAL * SDIM];
__device__ __half g_Hhi[(size_t)FINAL * SDIM];
__device__ __half g_WaH[SDIM * KPAD];
__device__ __half g_P1H[SDIM * SDIM];
__device__ __half g_P2H[QDIM * SDIM];
__device__ float g_bsum[SDIM];
__device__ __align__(16) char g_wblob[(size_t)NL * WBLOB];

// ---------------- helpers --------------------------------------------------
static __device__ __forceinline__ uint32_t smem_u32(const void* p) {
    uint32_t a;
    asm("{ .reg .u64 t; cvta.to.shared.u64 t, %1; cvt.u32.u64 %0, t; }"
        : "=r"(a) : "l"(p));
    return a;
}
static __device__ __forceinline__ void split_h(float v, __half& h, __half& l) {
    h = __float2half(v);
    l = __float2half(v - __half2float(h));
}
static __device__ __forceinline__ uint32_t sw(int t, int q) {
    return (uint32_t)((t << 6) + (((q ^ ((t >> 1) & 3))) << 4));
}

#define LDM4(R, a) \
    asm volatile("ldmatrix.sync.aligned.m8n8.x4.shared.b16 {%0,%1,%2,%3}, [%4];" \
        : "=r"((R)[0]), "=r"((R)[1]), "=r"((R)[2]), "=r"((R)[3]) : "r"(a))

#define MMA16816(C, A, B) \
    asm volatile("mma.sync.aligned.m16n8k16.row.col.f32.f16.f16.f32 " \
        "{%0,%1,%2,%3}, {%4,%5,%6,%7}, {%8,%9}, {%0,%1,%2,%3};" \
        : "+f"((C)[0]), "+f"((C)[1]), "+f"((C)[2]), "+f"((C)[3]) \
        : "r"((A)[0]), "r"((A)[1]), "r"((A)[2]), "r"((A)[3]), \
          "r"((B)[0]), "r"((B)[1]))

#define MMA16816H(C, A, B) \
    asm volatile("mma.sync.aligned.m16n8k16.row.col.f16.f16.f16.f16 " \
        "{%0,%1}, {%2,%3,%4,%5}, {%6,%7}, {%0,%1};" \
        : "+r"((C)[0]), "+r"((C)[1]) \
        : "r"((A)[0]), "r"((A)[1]), "r"((A)[2]), "r"((A)[3]), \
          "r"((B)[0]), "r"((B)[1]))

#define CPASYNC16(dst, src) \
    asm volatile("cp.async.cg.shared.global [%0], [%1], 16;" \
        :: "r"(dst), "l"(src) : "memory")

// ---------------- prep: weights (hi) for big GEMMs, sum skip bias ---------
__global__ __launch_bounds__(256) void prep_kernel(const float* __restrict__ wskip,
                                                   const float* __restrict__ bskip,
                                                   const float* __restrict__ wp1,
                                                   const float* __restrict__ wp2)
{
    int idx = blockIdx.x * 256 + threadIdx.x;
    if (idx < SDIM * KPAD) {
        int c = idx / KPAD, k = idx - c * KPAD;
        float v = 0.f;
        if (k < NL * RDC) {
            int i = k >> 5, r = k & 31;
            v = wskip[(size_t)i * SDIM * RDC + (size_t)c * RDC + r];
        }
        g_WaH[idx] = __float2half(v);
    }
    if (idx < SDIM * SDIM) g_P1H[idx] = __float2half(wp1[idx]);
    if (idx < QDIM * SDIM) g_P2H[idx] = __float2half(wp2[idx]);
    if (idx < SDIM) {
        float s = 0.f;
        #pragma unroll
        for (int i = 0; i < NL; i++) s += bskip[i * SDIM + idx];
        g_bsum[idx] = s;
    }
}

// ---------------- prep2: pack per-layer weights into swizzled blobs -------
__global__ __launch_bounds__(384) void prep2_kernel(const float* __restrict__ wt,
                                                    const float* __restrict__ bt,
                                                    const float* __restrict__ ws,
                                                    const float* __restrict__ bs,
                                                    const float* __restrict__ wd,
                                                    const float* __restrict__ bd)
{
    const int i = blockIdx.x;
    char* blob = g_wblob + (size_t)i * WBLOB;
    const float* wti = wt + (size_t)i * 3072;
    const float* wsi = ws + (size_t)i * 3072;
    const float* wdi = wd + (size_t)i * 1024;
    int tid = threadIdx.x;

    for (int idx = tid; idx < 6144; idx += 384) {
        int m = idx / 96, rem = idx - m * 96, r = rem / 3, j = rem - r * 3;
        float v = (m < 32) ? wti[m * 96 + r * 3 + j] : wsi[(m - 32) * 96 + r * 3 + j];
        __half h, l;
        split_h(v, h, l);
        uint32_t off = (uint32_t)(j * 4096) + sw(m, r >> 3) + (r & 7) * 2;
        *(__half*)(blob + off)         = h;
        *(__half*)(blob + 12288 + off) = l;
    }
    for (int idx = tid; idx < 1024; idx += 384) {
        int c = idx >> 5, r = idx & 31;
        __half h, l;
        split_h(wdi[idx], h, l);
        uint32_t off = sw(c, r >> 3) + (r & 7) * 2;
        *(__half*)(blob + 24576 + off) = h;
        *(__half*)(blob + 26624 + off) = l;
    }
    if (tid < 32) {
        float* bia = (float*)(blob + 28672);
        bia[tid]      = bt[i * 32 + tid];
        bia[32 + tid] = bs[i * 32 + tid];
        bia[64 + tid] = bd[i * 32 + tid];
    }
}

// ---------------- causal conv: 1 -> 32 ch, K=33; out time-major hi/lo ------
__global__ __launch_bounds__(256) void causal_kernel(const float* __restrict__ x,
                                                     const float* __restrict__ w,
                                                     const float* __restrict__ b,
                                                     __half* __restrict__ oh,
                                                     __half* __restrict__ ol)
{
    __shared__ float xsh[256 + KFILT - 1];
    __shared__ float wsh[KFILT * 32];
    __shared__ float bsh[32];
    int tid = threadIdx.x;
    int t0  = blockIdx.x * 256;

    for (int i = tid; i < 256 + KFILT - 1; i += 256) {
        int g = t0 + i;
        xsh[i] = (g < L_INPUT) ? x[g] : 0.f;
    }
    for (int i = tid; i < 32 * KFILT; i += 256) {
        int c = i / KFILT, k = i - c * KFILT;
        wsh[k * 32 + c] = w[i];
    }
    if (tid < 32) bsh[tid] = b[tid];
    __syncthreads();

    int c = tid & 31, lane = tid >> 5;
    for (int grp = 0; grp < 4; grp++) {
        int tl = lane * 32 + grp * 8;
        float acc[8];
        #pragma unroll
        for (int u = 0; u < 8; u++) acc[u] = bsh[c];
        #pragma unroll
        for (int k = 0; k < KFILT; k++) {
            float wv = wsh[k * 32 + c];
            #pragma unroll
            for (int u = 0; u < 8; u++) acc[u] += wv * xsh[tl + u + k];
        }
        #pragma unroll
        for (int u = 0; u < 8; u++) {
            int t = t0 + tl + u;
            if (t < L0) {
                __half h, l;
                split_h(acc[u], h, l);
                oh[(size_t)t * 32 + c] = h;
                ol[(size_t)t * 32 + c] = l;
            }
        }
    }
}

// ---------------- one layer pass over a staged 384-row tile ----------------
template<int D>
static __device__ __forceinline__ void layer_pass(
    char* smem, uint32_t sb,
    uint32_t IXH, uint32_t IXL, uint32_t SGH, uint32_t SGL, uint32_t BLOB,
    __half* __restrict__ Gh,
    int t0, int cut, int rowLim,
    __half* __restrict__ xouth, __half* __restrict__ xoutl, int L_out)
{
    const int tid = threadIdx.x;
    const int l    = tid & 31;
    const int w    = tid >> 5;
    const int grp  = l >> 3, mrow = l & 7;
    const int tw   = w * 32;
    const float* bia = (const float*)(smem + BLOB + 28672);

    float acc[4][4][4];
    #pragma unroll
    for (int mi = 0; mi < 4; mi++) {
        float b0 = bia[mi * 16 + (l >> 2)];
        float b8 = bia[mi * 16 + (l >> 2) + 8];
        #pragma unroll
        for (int ni = 0; ni < 4; ni++) {
            acc[mi][ni][0] = b0; acc[mi][ni][1] = b0;
            acc[mi][ni][2] = b8; acc[mi][ni][3] = b8;
        }
    }

    #pragma unroll
    for (int j = 0; j < 3; j++) {
        #pragma unroll
        for (int kc = 0; kc < 2; kc++) {
            uint32_t a4[4][4], b1[4][2];
            #pragma unroll
            for (int h2 = 0; h2 < 2; h2++) {
                int t = tw + j * D + h2 * 16 + ((grp >> 1) << 3) + mrow;
                int q = kc * 2 + (grp & 1);
                uint32_t R[4];
                LDM4(R, sb + IXH + sw(t, q));
                b1[h2 * 2][0] = R[0]; b1[h2 * 2][1] = R[1];
                b1[h2 * 2 + 1][0] = R[2]; b1[h2 * 2 + 1][1] = R[3];
            }
            int tm = ((grp & 1) << 3) + mrow;
            int qa = kc * 2 + (grp >> 1);
            #pragma unroll
            for (int mi = 0; mi < 4; mi++)
                LDM4(a4[mi], sb + BLOB + j * 4096 + sw(mi * 16 + tm, qa));
            #pragma unroll
            for (int mi = 0; mi < 4; mi++)
                #pragma unroll
                for (int ni = 0; ni < 4; ni++)
                    MMA16816(acc[mi][ni], a4[mi], b1[ni]);
            #pragma unroll
            for (int mi = 0; mi < 4; mi++)
                LDM4(a4[mi], sb + BLOB + 12288 + j * 4096 + sw(mi * 16 + tm, qa));
            #pragma unroll
            for (int mi = 0; mi < 4; mi++)
                #pragma unroll
                for (int ni = 0; ni < 4; ni++)
                    MMA16816(acc[mi][ni], a4[mi], b1[ni]);
        }
    }

    #pragma unroll
    for (int mi = 0; mi < 2; mi++)
        #pragma unroll
        for (int ni = 0; ni < 4; ni++)
            #pragma unroll
            for (int jj = 0; jj < 4; jj++) {
                float a1 = fminf(fmaxf(acc[mi][ni][jj], -30.f), 30.f);
                float a2 = fminf(fmaxf(acc[mi + 2][ni][jj], -30.f), 30.f);
                float u  = 1.f + __expf(-2.f * a1);
                float vv = 1.f + __expf(-a2);
                float gv = __fdividef(2.f - u, u * vv);
                int t_loc = tw + ni * 8 + 2 * (l & 3) + (jj & 1);
                int c     = mi * 16 + (l >> 2) + ((jj >= 2) ? 8 : 0);
                __half h, lo2;
                split_h(gv, h, lo2);
                uint32_t off = sw(t_loc, c >> 3) + (c & 7) * 2;
                *(__half*)(smem + SGH + off) = h;
                *(__half*)(smem + SGL + off) = lo2;
            }
    __syncwarp();

    {
        int row = tw + l;
        int uo  = t0 + row - cut;
        if (row < rowLim && uo >= 0 && uo < FINAL) {
            char* dh = (char*)(Gh + (size_t)uo * KPAD);
            #pragma unroll
            for (int q = 0; q < 4; q++)
                *(uint4*)(dh + q * 16) = *(uint4*)(smem + SGH + sw(row, q));
        }
    }

    float dacc[2][4][4];
    uint32_t hacc[2][4][2];
    #pragma unroll
    for (int mi = 0; mi < 2; mi++) {
        float b0 = bia[64 + mi * 16 + (l >> 2)];
        float b8 = bia[64 + mi * 16 + (l >> 2) + 8];
        #pragma unroll
        for (int ni = 0; ni < 4; ni++) {
            dacc[mi][ni][0] = b0; dacc[mi][ni][1] = b0;
            dacc[mi][ni][2] = b8; dacc[mi][ni][3] = b8;
            hacc[mi][ni][0] = 0u; hacc[mi][ni][1] = 0u;
        }
    }
    #pragma unroll
    for (int kc = 0; kc < 2; kc++) {
        uint32_t a4[2][4], b1[4][2], b2[4][2];
        #pragma unroll
        for (int h2 = 0; h2 < 2; h2++) {
            int t = tw + h2 * 16 + ((grp >> 1) << 3) + mrow;
            int q = kc * 2 + (grp & 1);
            uint32_t R[4];
            LDM4(R, sb + SGH + sw(t, q));
            b1[h2 * 2][0] = R[0]; b1[h2 * 2][1] = R[1];
            b1[h2 * 2 + 1][0] = R[2]; b1[h2 * 2 + 1][1] = R[3];
            LDM4(R, sb + SGL + sw(t, q));
            b2[h2 * 2][0] = R[0]; b2[h2 * 2][1] = R[1];
            b2[h2 * 2 + 1][0] = R[2]; b2[h2 * 2 + 1][1] = R[3];
        }
        int tm = ((grp & 1) << 3) + mrow;
        int qa = kc * 2 + (grp >> 1);
        #pragma unroll
        for (int mi = 0; mi < 2; mi++)
            LDM4(a4[mi], sb + BLOB + 24576 + sw(mi * 16 + tm, qa));
        #pragma unroll
        for (int mi = 0; mi < 2; mi++)
            #pragma unroll
            for (int ni = 0; ni < 4; ni++) {
                MMA16816(dacc[mi][ni], a4[mi], b1[ni]);
                MMA16816H(hacc[mi][ni], a4[mi], b2[ni]);
            }
        #pragma unroll
        for (int mi = 0; mi < 2; mi++)
            LDM4(a4[mi], sb + BLOB + 26624 + sw(mi * 16 + tm, qa));
        #pragma unroll
        for (int mi = 0; mi < 2; mi++)
            #pragma unroll
            for (int ni = 0; ni < 4; ni++)
                MMA16816H(hacc[mi][ni], a4[mi], b1[ni]);
    }
    __syncwarp();

    #pragma unroll
    for (int mi = 0; mi < 2; mi++)
        #pragma unroll
        for (int ni = 0; ni < 4; ni++) {
            __half2 h01 = *(__half2*)&hacc[mi][ni][0];
            __half2 h23 = *(__half2*)&hacc[mi][ni][1];
            float cr[4] = {__low2float(h01), __high2float(h01),
                           __low2float(h23), __high2float(h23)};
            #pragma unroll
            for (int jj = 0; jj < 4; jj++) {
                int t_loc = tw + ni * 8 + 2 * (l & 3) + (jj & 1);
                int c     = mi * 16 + (l >> 2) + ((jj >= 2) ? 8 : 0);
                uint32_t offx = sw(t_loc + D, c >> 3) + (c & 7) * 2;
                float xv = __half2float(*(__half*)(smem + IXH + offx))
                         + __half2float(*(__half*)(smem + IXL + offx));
                float ov = dacc[mi][ni][jj] + cr[jj] + xv;
                __half h, lo2;
                split_h(ov, h, lo2);
                uint32_t off = sw(t_loc, c >> 3) + (c & 7) * 2;
                *(__half*)(smem + SGH + off) = h;
                *(__half*)(smem + SGL + off) = lo2;
            }
        }
    __syncwarp();

    if (xouth) {
        int row = tw + l;
        int t   = t0 + row;
        if (row < rowLim && t < L_out) {
            char* dh = (char*)(xouth + (size_t)t * 32);
            char* dl = (char*)(xoutl + (size_t)t * 32);
            #pragma unroll
            for (int q = 0; q < 4; q++) {
                *(uint4*)(dh + q * 16) = *(uint4*)(smem + SGH + sw(row, q));
                *(uint4*)(dl + q * 16) = *(uint4*)(smem + SGL + sw(row, q));
            }
        }
    }
}

// ---------------- single-layer kernel --------------------------------------
template<int D>
__global__ __launch_bounds__(384, 1) void layer_mma(
    const __half* __restrict__ xinh, const __half* __restrict__ xinl,
    __half* __restrict__ xouth, __half* __restrict__ xoutl,
    const char* __restrict__ wblob,
    __half* __restrict__ Gh,
    int L_in, int L_out, int cut)
{
    constexpr int RT = 384 + 2 * D;
    constexpr int XH  = 0;
    constexpr int XL  = RT * 64;
    constexpr int BL  = 2 * RT * 64;
    constexpr int STH = BL + WBLOB;
    constexpr int STL = STH + 24576;

    extern __shared__ char smem[];
    const uint32_t sb = smem_u32(smem);
    const int tid = threadIdx.x;
    const int t0  = blockIdx.x * 384;

    for (int idx = tid; idx < WBLOB / 16; idx += 384)
        CPASYNC16(sb + BL + idx * 16, wblob + idx * 16);

    for (int idx = tid; idx < RT * 4; idx += 384) {
        int t = idx >> 2, q = idx & 3;
        uint32_t so = sw(t, q);
        if (t0 + t < L_in) {
            CPASYNC16(sb + XH + so, xinh + (size_t)(t0 + t) * 32 + q * 8);
            CPASYNC16(sb + XL + so, xinl + (size_t)(t0 + t) * 32 + q * 8);
        } else {
            uint4 z = make_uint4(0, 0, 0, 0);
            *(uint4*)(smem + XH + so) = z;
            *(uint4*)(smem + XL + so) = z;
        }
    }
    asm volatile("cp.async.commit_group;" ::: "memory");
    asm volatile("cp.async.wait_group 0;" ::: "memory");
    __syncthreads();

    layer_pass<D>(smem, sb, XH, XL, STH, STL, BL, Gh,
                  t0, cut, 384, xouth, xoutl, L_out);
}

#define LAYER_SMEM_B(D_) (2 * (384 + 2 * (D_)) * 64 + WBLOB + 384 * 64 * 2)

// ---------------- fused two-layer kernel (dilations D1, D2=2*D1) -----------
template<int D1, int D2>
__global__ __launch_bounds__(384, 1) void layer2_mma(
    const __half* __restrict__ xinh, const __half* __restrict__ xinl,
    __half* __restrict__ xouth, __half* __restrict__ xoutl,
    const char* __restrict__ wblob,
    __half* __restrict__ Gh,
    int L_in, int L_out2, int cut1, int cut2)
{
    constexpr int RT1  = 384 + 2 * D1;
    constexpr int SRT  = 384 + 2 * D2;
    constexpr int SOUT = 384 - 2 * D2;
    constexpr int XH  = 0;
    constexpr int XL  = RT1 * 64;
    constexpr int BL  = 2 * RT1 * 64;
    constexpr int STH = BL + 2 * WBLOB;
    constexpr int STL = STH + SRT * 64;

    extern __shared__ char smem[];
    const uint32_t sb = smem_u32(smem);
    const int tid = threadIdx.x;
    const int t0  = blockIdx.x * SOUT;

    for (int idx = tid; idx < 2 * WBLOB / 16; idx += 384)
        CPASYNC16(sb + BL + idx * 16, wblob + idx * 16);

    for (int idx = tid; idx < RT1 * 4; idx += 384) {
        int t = idx >> 2, q = idx & 3;
        uint32_t so = sw(t, q);
        if (t0 + t < L_in) {
            CPASYNC16(sb + XH + so, xinh + (size_t)(t0 + t) * 32 + q * 8);
            CPASYNC16(sb + XL + so, xinl + (size_t)(t0 + t) * 32 + q * 8);
        } else {
            uint4 z = make_uint4(0, 0, 0, 0);
            *(uint4*)(smem + XH + so) = z;
            *(uint4*)(smem + XL + so) = z;
        }
    }
    asm volatile("cp.async.commit_group;" ::: "memory");
    asm volatile("cp.async.wait_group 0;" ::: "memory");
    __syncthreads();

    layer_pass<D1>(smem, sb, XH, XL, STH, STL, BL, Gh,
                   t0, cut1, 384, (__half*)nullptr, (__half*)nullptr, 0);
    __syncthreads();
    layer_pass<D2>(smem, sb, STH, STL, XH, XL, BL + WBLOB, Gh + 32,
                   t0, cut2, SOUT, xouth, xoutl, L_out2);
}

#define LAYER2_SMEM_B(D1_, D2_) (2 * (384 + 2 * (D1_)) * 64 + 2 * WBLOB \
                                 + 2 * (384 + 2 * (D2_)) * 64)

// ---------------- GEMM: 256 threads, 128x64 tile, Ah*Bh only, 2 CTAs/SM ---
#define GSTG  24576
#define GSMEM (3 * GSTG)
__global__ __launch_bounds__(256, 2) void gemm_mma(
    const __half* __restrict__ Ah, const __half* __restrict__ Bh,
    const float* __restrict__ bias, int Kstr, int NC, int mode,
    __half* __restrict__ Ch, int Cstr, float* __restrict__ Cf)
{
    extern __shared__ char smem[];
    const uint32_t sb = smem_u32(smem);
    const int tid = threadIdx.x;
    const int m0 = blockIdx.x << 7, n0 = blockIdx.y << 6;
    const int lane = tid & 31;
    const int wm = (tid >> 5) & 3, wn = tid >> 7;

    float acc[8][4];
    #pragma unroll
    for (int i = 0; i < 8; i++)
        #pragma unroll
        for (int j = 0; j < 4; j++) acc[i][j] = 0.f;

    auto issue = [&](int c) {
        uint32_t buf = (uint32_t)(c % 3) * GSTG;
        int kc0 = c << 6;
        int rloc = tid >> 3, q = tid & 7;
        #pragma unroll
        for (int it = 0; it < 6; it++) {
            const __half* src;
            uint32_t dst;
            if (it < 4) {                       // A: 128 rows
                int rr = (it << 5) + rloc;
                src = Ah + (size_t)(m0 + rr) * Kstr + kc0 + q * 8;
                uint32_t off = (uint32_t)(rr * 128 + q * 16);
                off ^= (off >> 3) & 0x70;
                dst = sb + buf + off;
            } else {                            // Bh: 64 rows
                int rr = ((it - 4) << 5) + rloc;
                src = Bh + (size_t)(n0 + rr) * Kstr + kc0 + q * 8;
                uint32_t off = (uint32_t)(rr * 128 + q * 16);
                off ^= (off >> 3) & 0x70;
                dst = sb + buf + 16384u + off;
            }
            CPASYNC16(dst, src);
        }
        asm volatile("cp.async.commit_group;" ::: "memory");
    };

    issue(0);
    if (NC > 1) issue(1);
    for (int c = 0; c < NC; c++) {
        if (c + 1 < NC) {
            asm volatile("cp.async.wait_group 1;" ::: "memory");
        } else {
            asm volatile("cp.async.wait_group 0;" ::: "memory");
        }
        __syncthreads();
        if (c + 2 < NC) issue(c + 2);
        const uint32_t buf = sb + (uint32_t)(c % 3) * GSTG;

        #pragma unroll
        for (int ks = 0; ks < 4; ks++) {
            uint32_t ah[2][4], bh[4][2];
            #pragma unroll
            for (int mi = 0; mi < 2; mi++) {
                uint32_t row = wm * 32 + mi * 16 + (lane & 15);
                uint32_t ch  = ks * 2 + (lane >> 4);
                uint32_t off = row * 128 + ch * 16;
                off ^= (off >> 3) & 0x70;
                LDM4(ah[mi], buf + off);
            }
            #pragma unroll
            for (int nj = 0; nj < 2; nj++) {
                uint32_t row = wn * 32 + nj * 16 + (lane & 7) + ((lane >> 4) << 3);
                uint32_t ch  = ks * 2 + ((lane >> 3) & 1);
                uint32_t off = row * 128 + ch * 16;
                off ^= (off >> 3) & 0x70;
                uint32_t r4[4];
                LDM4(r4, buf + 16384u + off);
                bh[nj * 2][0] = r4[0]; bh[nj * 2][1] = r4[1];
                bh[nj * 2 + 1][0] = r4[2]; bh[nj * 2 + 1][1] = r4[3];
            }
            #pragma unroll
            for (int mi = 0; mi < 2; mi++)
                #pragma unroll
                for (int nt = 0; nt < 4; nt++)
                    MMA16816(acc[mi * 4 + nt], ah[mi], bh[nt]);
        }
    }
    __syncthreads();

    float* cs = (float*)smem;
    #pragma unroll
    for (int mi = 0; mi < 2; mi++)
        #pragma unroll
        for (int nt = 0; nt < 4; nt++) {
            float* C = acc[mi * 4 + nt];
            int mrow = wm * 32 + mi * 16 + (lane >> 2);
            int ncol = wn * 32 + nt * 8 + 2 * (lane & 3);
            cs[ncol * 132 + mrow]           = C[0];
            cs[(ncol + 1) * 132 + mrow]     = C[1];
            cs[ncol * 132 + mrow + 8]       = C[2];
            cs[(ncol + 1) * 132 + mrow + 8] = C[3];
        }
    __syncthreads();

    if (mode) {
        #pragma unroll
        for (int it = 0; it < 16; it++) {
            int idx = it * 256 + tid;
            int n = idx >> 6, mp = idx & 63;
            float2 v2 = *(float2*)&cs[n * 132 + 2 * mp];
            float b0 = __ldg(bias + m0 + 2 * mp);
            float b1 = __ldg(bias + m0 + 2 * mp + 1);
            float v0 = fmaxf(v2.x + b0, 0.f);
            float v1 = fmaxf(v2.y + b1, 0.f);
            __half h0 = __float2half(v0);
            __half h1 = __float2half(v1);
            uint32_t ph = (uint32_t)__half_as_ushort(h0) |
                          ((uint32_t)__half_as_ushort(h1) << 16);
            size_t o = (size_t)(n0 + n) * Cstr + m0 + 2 * mp;
            *(uint32_t*)(Ch + o) = ph;
        }
    } else {
        #pragma unroll
        for (int it = 0; it < 32; it++) {
            int idx = it * 256 + tid;
            int n = idx & 63, m = idx >> 6;
            float v = cs[n * 132 + m] + __ldg(bias + m0 + m);
            Cf[(size_t)(m0 + m) * FINAL + n0 + n] = v;
        }
    }
}

// ---------------- launch --------------------------------------------------
extern "C" void kernel_launch(void* const* d_in, const int* in_sizes, int n_in,
                              void* d_out, int out_size)
{
    const float* x        = (const float*)d_in[0];
    const float* w_causal = (const float*)d_in[1];
    const float* b_causal = (const float*)d_in[2];
    const float* w_tanh   = (const float*)d_in[3];
    const float* b_tanh   = (const float*)d_in[4];
    const float* w_sig    = (const float*)d_in[5];
    const float* b_sig    = (const float*)d_in[6];
    const float* w_skip   = (const float*)d_in[7];
    const float* b_skip   = (const float*)d_in[8];
    const float* w_dense  = (const float*)d_in[9];
    const float* b_dense  = (const float*)d_in[10];
    const float* w_post1  = (const float*)d_in[11];
    const float* b_post1  = (const float*)d_in[12];
    const float* w_post2  = (const float*)d_in[13];
    const float* b_post2  = (const float*)d_in[14];

    float *bsum;
    __half *xah, *xal, *xbh, *xbl;
    __half *Ghi, *Shi, *Hhi;
    __half *WaH, *P1H, *P2H;
    char* wblob;
    cudaGetSymbolAddress((void**)&xah, g_xah);
    cudaGetSymbolAddress((void**)&xal, g_xal);
    cudaGetSymbolAddress((void**)&xbh, g_xbh);
    cudaGetSymbolAddress((void**)&xbl, g_xbl);
    cudaGetSymbolAddress((void**)&Ghi, g_Ghi);
    cudaGetSymbolAddress((void**)&Shi, g_Shi);
    cudaGetSymbolAddress((void**)&Hhi, g_Hhi);
    cudaGetSymbolAddress((void**)&WaH, g_WaH);
    cudaGetSymbolAddress((void**)&P1H, g_P1H);
    cudaGetSymbolAddress((void**)&P2H, g_P2H);
    cudaGetSymbolAddress((void**)&bsum, g_bsum);
    cudaGetSymbolAddress((void**)&wblob, g_wblob);

    cudaFuncSetAttribute(gemm_mma,
                         cudaFuncAttributeMaxDynamicSharedMemorySize, GSMEM);

    prep_kernel<<<(SDIM * KPAD + 255) / 256, 256>>>(w_skip, b_skip, w_post1, w_post2);
    prep2_kernel<<<NL, 384>>>(w_tanh, b_tanh, w_sig, b_sig, w_dense, b_dense);
    causal_kernel<<<(L0 + 255) / 256, 256>>>(x, w_causal, b_causal, xah, xal);

    __half *curh = xah, *curl = xal, *nxth = xbh, *nxtl = xbl;
    int L = L0;
    int i = 0;
    while (i < NL) {
        int k = i % 9;
        int d = 1 << k;
        bool fuse = (i + 1 < NL) && (k == 0 || k == 2 || k == 4);
        if (fuse) {
            int d2   = d * 2;
            int Lmid = L - 2 * d;
            int Lout2 = Lmid - 2 * d2;
            int cut1 = (Lmid - FINAL) / 2;
            int cut2 = (Lout2 - FINAL) / 2;
            int SOUT = 384 - 2 * d2;

            void (*kfn)(const __half*, const __half*, __half*, __half*,
                        const char*, __half*, int, int, int, int) = nullptr;
            size_t smem = 0;
            switch (d) {
                case 1:  kfn = layer2_mma<1, 2>;   smem = LAYER2_SMEM_B(1, 2);   break;
                case 4:  kfn = layer2_mma<4, 8>;   smem = LAYER2_SMEM_B(4, 8);   break;
                case 16: kfn = layer2_mma<16, 32>; smem = LAYER2_SMEM_B(16, 32); break;
            }
            cudaFuncSetAttribute(kfn, cudaFuncAttributeMaxDynamicSharedMemorySize,
                                 (int)smem);
            kfn<<<(Lout2 + SOUT - 1) / SOUT, 384, smem>>>(
                curh, curl, nxth, nxtl,
                wblob + (size_t)i * WBLOB,
                Ghi + i * 32,
                L, Lout2, cut1, cut2);
            L = Lout2;
            i += 2;
        } else {
            int Lout = L - 2 * d;
            int cut  = (Lout - FINAL) / 2;
            void (*kfn)(const __half*, const __half*, __half*, __half*,
                        const char*, __half*, int, int, int) = nullptr;
            size_t smem = 0;
            switch (d) {
                case 1:   kfn = layer_mma<1>;   smem = LAYER_SMEM_B(1);   break;
                case 2:   kfn = layer_mma<2>;   smem = LAYER_SMEM_B(2);   break;
                case 4:   kfn = layer_mma<4>;   smem = LAYER_SMEM_B(4);   break;
                case 8:   kfn = layer_mma<8>;   smem = LAYER_SMEM_B(8);   break;
                case 16:  kfn = layer_mma<16>;  smem = LAYER_SMEM_B(16);  break;
                case 32:  kfn = layer_mma<32>;  smem = LAYER_SMEM_B(32);  break;
                case 64:  kfn = layer_mma<64>;  smem = LAYER_SMEM_B(64);  break;
                case 128: kfn = layer_mma<128>; smem = LAYER_SMEM_B(128); break;
                case 256: kfn = layer_mma<256>; smem = LAYER_SMEM_B(256); break;
            }
            cudaFuncSetAttribute(kfn, cudaFuncAttributeMaxDynamicSharedMemorySize,
                                 (int)smem);
            kfn<<<(Lout + 383) / 384, 384, smem>>>(
                curh, curl, nxth, nxtl,
                wblob + (size_t)i * WBLOB,
                Ghi + i * 32,
                L, Lout, cut);
            L = Lout;
            i += 1;
        }
        __half* t;
        t = curh; curh = nxth; nxth = t;
        t = curl; curl = nxtl; nxtl = t;
    }

    // skip GEMM: S = relu(Wa @ Ghi + bsum)   M=512, K=1472, N=160000
    gemm_mma<<<dim3(SDIM / 128, FINAL / 64), 256, GSMEM>>>(
        WaH, Ghi, bsum, KPAD, KPAD / 64, 1, Shi, SDIM, nullptr);
    // post1: H = relu(W1 @ Shi + b1)         M=512, K=512
    gemm_mma<<<dim3(SDIM / 128, FINAL / 64), 256, GSMEM>>>(
        P1H, Shi, b_post1, SDIM, SDIM / 64, 1, Hhi, SDIM, nullptr);
    // post2: out = W2 @ Hhi + b2             M=256, K=512, fp32 channel-major
    gemm_mma<<<dim3(QDIM / 128, FINAL / 64), 256, GSMEM>>>(
        P2H, Hhi, b_post2, SDIM, SDIM / 64, 0, nullptr, 0, (float*)d_out);
}